// round 11
// baseline (speedup 1.0000x reference)
#include <cuda_runtime.h>
#include <cuda_fp16.h>
#include <cstdint>
#include <cstddef>

#define H        256
#define AF       39
#define BF       11
#define KI       50
#define KO_REAL  295
#define KO_PAD   320
#define EMAX     380000
#define NMAX     200000
#define BM       64
#define LDA2     40            // k_out A stage stride (halves)

// ---- k_msg (BM=128, 512 thr) smem: resident A + 2-stage B ----
#define MSG_AH     0
#define MSG_AL     67584                 // 128 * 528
#define MSG_B      135168
#define MSG_BSTAGE 40960                 // per stage: 20480 hi + 20480 lo
#define SMEM_MSG   217088

// ---- k_out smem layout (256 thr, BM=64) ----
#define OFF_AH(b)  ((b) * 10240)
#define OFF_AL(b)  ((b) * 10240 + 5120)
#define OFF_BH(b)  (20480 + (b) * 40960)
#define OFF_BL(b)  (20480 + (b) * 40960 + 20480)
#define SMEM_TC    102400

// ---------------- scratch (device globals) ----------------------------------
__device__ float g_msg_input[(size_t)EMAX * H];
__device__ float g_msgA[(size_t)EMAX * H];
__device__ float g_msgB[(size_t)EMAX * H];
__device__ float g_S0[(size_t)NMAX * H];
__device__ float g_S1[(size_t)NMAX * H];
__device__ float g_WiT[KI * H];
__device__ __half g_Wh_hi[H * H];
__device__ __half g_Wh_lo[H * H];
__device__ __half g_Wo_hi[H * KO_PAD];
__device__ __half g_Wo_lo[H * KO_PAD];

// ---------------- helpers ----------------------------------------------------
__device__ __forceinline__ void red_add4(float* p, float a, float b, float c, float d) {
  asm volatile("red.global.add.v4.f32 [%0], {%1,%2,%3,%4};"
               :: "l"(p), "f"(a), "f"(b), "f"(c), "f"(d) : "memory");
}
__device__ __forceinline__ void red_add2(float* p, float a, float b) {
  asm volatile("red.global.add.v2.f32 [%0], {%1,%2};"
               :: "l"(p), "f"(a), "f"(b) : "memory");
}
__device__ __forceinline__ uint32_t smem_u32(const void* p) {
  return (uint32_t)__cvta_generic_to_shared(p);
}
__device__ __forceinline__ void ldm4(uint32_t* r, uint32_t addr) {
  asm volatile("ldmatrix.sync.aligned.m8n8.x4.shared.b16 {%0,%1,%2,%3}, [%4];"
               : "=r"(r[0]), "=r"(r[1]), "=r"(r[2]), "=r"(r[3]) : "r"(addr));
}
__device__ __forceinline__ void mma16816(float* c, const uint32_t* a, const uint32_t* b) {
  asm volatile("mma.sync.aligned.m16n8k16.row.col.f32.f16.f16.f32 "
               "{%0,%1,%2,%3}, {%4,%5,%6,%7}, {%8,%9}, {%0,%1,%2,%3};"
               : "+f"(c[0]), "+f"(c[1]), "+f"(c[2]), "+f"(c[3])
               : "r"(a[0]), "r"(a[1]), "r"(a[2]), "r"(a[3]),
                 "r"(b[0]), "r"(b[1]));
}
#define CP16(dst, src) \
  asm volatile("cp.async.cg.shared.global [%0], [%1], 16;" :: "r"(dst), "l"(src))
#define CP_COMMIT() asm volatile("cp.async.commit_group;" ::: "memory")
#define CP_WAIT(n)  asm volatile("cp.async.wait_group %0;" :: "n"(n) : "memory")

// ---------------- fused prep ---------------------------------------------------
// W_o k-permuted: [S(256) | x(39) | pad]
__global__ void k_prep(float* __restrict__ WiT, const float* __restrict__ W_i,
                       __half* __restrict__ WhH, __half* __restrict__ WhL,
                       const float* __restrict__ W_h,
                       __half* __restrict__ WoH, __half* __restrict__ WoL,
                       const float* __restrict__ W_o) {
  int idx = blockIdx.x * 256 + threadIdx.x;
  if (idx < KI * H) {
    int k = idx >> 8, h = idx & (H - 1);
    WiT[idx] = W_i[h * KI + k];
  }
  if (idx < H * H) {
    float v = W_h[idx];
    __half hh = __float2half_rn(v);
    WhH[idx] = hh;
    WhL[idx] = __float2half_rn(v - __half2float(hh));
  }
  if (idx < H * KO_PAD) {
    int n = idx / KO_PAD, k = idx - n * KO_PAD;
    float v = 0.f;
    if (k < H)            v = W_o[n * KO_REAL + AF + k];
    else if (k < KO_REAL) v = W_o[n * KO_REAL + (k - H)];
    __half hh = __float2half_rn(v);
    WoH[idx] = hh;
    WoL[idx] = __float2half_rn(v - __half2float(hh));
  }
}

// ---------------- init (SIMT, K=50) + fused scatter into S0 -------------------
__global__ __launch_bounds__(256) void k_init(
    const float* __restrict__ x, const float* __restrict__ bond,
    const int* __restrict__ esrc, const int* __restrict__ edst,
    const float* __restrict__ WiT,
    float* __restrict__ msg_input, float* __restrict__ S0, int E)
{
  extern __shared__ float smf[];
  float* As = smf;                // [KI][BM]
  float* Bs = smf + KI * BM;      // [KI][H]
  __shared__ int s_src[BM];

  int tid = threadIdx.x;
  int bm  = blockIdx.x * BM;
  if (tid < BM) {
    int e = bm + tid;
    s_src[tid] = (e < E) ? esrc[e] : 0;
  }
  __syncthreads();

  for (int i = tid; i < KI * BM; i += 256) {
    int k = i >> 6, m = i & (BM - 1);
    int e = bm + m;
    float v = 0.f;
    if (e < E) v = (k < AF) ? x[(size_t)s_src[m] * AF + k]
                            : bond[(size_t)e * BF + (k - AF)];
    As[k * BM + m] = v;
  }
  for (int i = tid; i < KI * (H / 4); i += 256) {
    int k = i >> 6;
    int h4 = (i & 63) * 4;
    *(float4*)&Bs[k * H + h4] = *(const float4*)&WiT[k * H + h4];
  }
  __syncthreads();

  int tm = tid >> 5, tn = tid & 31;
  float acc[8][8];
#pragma unroll
  for (int i = 0; i < 8; i++)
#pragma unroll
    for (int j = 0; j < 8; j++) acc[i][j] = 0.f;

  for (int k = 0; k < KI; k++) {
    float a[8], b[8];
    *(float4*)(a)     = *(float4*)&As[k * BM + tm * 8];
    *(float4*)(a + 4) = *(float4*)&As[k * BM + tm * 8 + 4];
    *(float4*)(b)     = *(float4*)&Bs[k * H + tn * 8];
    *(float4*)(b + 4) = *(float4*)&Bs[k * H + tn * 8 + 4];
#pragma unroll
    for (int i = 0; i < 8; i++)
#pragma unroll
      for (int j = 0; j < 8; j++)
        acc[i][j] = fmaf(a[i], b[j], acc[i][j]);
  }

#pragma unroll
  for (int i = 0; i < 8; i++) {
    int e = bm + tm * 8 + i;
    if (e >= E) continue;
    int d = edst[e];
    size_t base = (size_t)e * H + tn * 8;
    float4 o0, o1;
    o0.x = acc[i][0]; o0.y = acc[i][1]; o0.z = acc[i][2]; o0.w = acc[i][3];
    o1.x = acc[i][4]; o1.y = acc[i][5]; o1.z = acc[i][6]; o1.w = acc[i][7];
    *(float4*)(msg_input + base)     = o0;
    *(float4*)(msg_input + base + 4) = o1;
    float* sp = S0 + (size_t)d * H + tn * 8;
    red_add4(sp,     fmaxf(o0.x, 0.f), fmaxf(o0.y, 0.f), fmaxf(o0.z, 0.f), fmaxf(o0.w, 0.f));
    red_add4(sp + 4, fmaxf(o1.x, 0.f), fmaxf(o1.y, 0.f), fmaxf(o1.z, 0.f), fmaxf(o1.w, 0.f));
  }
}

// ---------------- message GEMM: resident-A, 2-stage B, ldmatrix --------------
// msg_out[e] = relu(msg_input[e] + (S[src[e]] - msg_cur[rev(e)]) @ W_h^T)
__global__ __launch_bounds__(512, 1) void k_msg(
    const float* __restrict__ S, const float* __restrict__ msg_cur,
    const float* __restrict__ msg_input,
    const __half* __restrict__ Wh_hi, const __half* __restrict__ Wh_lo,
    const int* __restrict__ esrc, const int* __restrict__ edst,
    float* __restrict__ msg_out, float* __restrict__ Snext, int E, int relu_rev)
{
  extern __shared__ __align__(16) char smc[];
  uint32_t sb = smem_u32(smc);
  int tid = threadIdx.x, wid = tid >> 5, lane = tid & 31;
  int wm = wid & 3, wn = wid >> 2;          // 4 m-warps x 4 n-warps
  int gid = lane >> 2, tig = lane & 3;
  int bm = blockIdx.x * 128;

  int row = tid >> 2;           // 0..127 (gather row)
  int q   = tid & 3;
  int e = bm + row;
  bool ev = e < E;
  int eh = E >> 1;
  int sidx = 0, ridx = 0;
  if (ev) { sidx = __ldg(esrc + e); ridx = (e < eh) ? (e + eh) : (e - eh); }
  const float* Sp = S       + (size_t)sidx * H;
  const float* Rp = msg_cur + (size_t)ridx * H;

  // B copy: thread pairs split hi/lo rows
  int bRow  = tid >> 1;
  int bHalf = tid & 1;
  const char* Wsrc = (const char*)((bHalf ? Wh_lo : Wh_hi) + (size_t)bRow * H);

  int lrow = (lane & 7) + ((lane >> 3) & 1) * 8;
  int lcol = (lane >> 4) * 8;

  // ldmatrix.x4 B base: lanes 0-7 bh k-lo, 8-15 bh k+8, 16-23 bl k-lo, 24-31 bl k+8
  int selB = lane >> 3;
  uint32_t bLaneBase = (uint32_t)MSG_B + (uint32_t)((selB >> 1) * 20480)
                     + (uint32_t)((wn * 64 + (lane & 7)) * 80)
                     + (uint32_t)((selB & 1) * 16);

  float acc[2][8][4];
#pragma unroll
  for (int mi = 0; mi < 2; mi++)
#pragma unroll
    for (int ni = 0; ni < 8; ni++)
#pragma unroll
      for (int qq = 0; qq < 4; qq++) acc[mi][ni][qq] = 0.f;

  auto cpB = [&](int kc, int buf) {
    const char* s = Wsrc + kc * 64;
    uint32_t d = sb + MSG_B + (uint32_t)buf * MSG_BSTAGE
               + (uint32_t)(bHalf * 20480) + (uint32_t)bRow * 80;
#pragma unroll
    for (int i = 0; i < 4; i++) CP16(d + i * 16, s + i * 16);
    CP_COMMIT();
  };

  // ---- prologue: start both B stages (they ride under the gather) ----
  cpB(0, 0);
  cpB(1, 1);

  // ---- producer: gather full 128x256 diff tile into resident A (hi/lo) ----
  // thread covers cols [j*32 + q*8, +8) for j = 0..7; conflict-free STS.128.
  {
    uint32_t rowByte = (uint32_t)row * 528;
#pragma unroll
    for (int j = 0; j < 8; j++) {
      int col = j * 32 + q * 8;
      float4 s0, s1, r0, r1;
      if (ev) {
        s0 = *(const float4*)(Sp + col);
        s1 = *(const float4*)(Sp + col + 4);
        r0 = *(const float4*)(Rp + col);
        r1 = *(const float4*)(Rp + col + 4);
        if (relu_rev) {
          r0.x = fmaxf(r0.x, 0.f); r0.y = fmaxf(r0.y, 0.f);
          r0.z = fmaxf(r0.z, 0.f); r0.w = fmaxf(r0.w, 0.f);
          r1.x = fmaxf(r1.x, 0.f); r1.y = fmaxf(r1.y, 0.f);
          r1.z = fmaxf(r1.z, 0.f); r1.w = fmaxf(r1.w, 0.f);
        }
      } else {
        s0 = s1 = r0 = r1 = make_float4(0.f, 0.f, 0.f, 0.f);
      }
      float a[8];
      a[0] = s0.x - r0.x; a[1] = s0.y - r0.y; a[2] = s0.z - r0.z; a[3] = s0.w - r0.w;
      a[4] = s1.x - r1.x; a[5] = s1.y - r1.y; a[6] = s1.z - r1.z; a[7] = s1.w - r1.w;
      __half hh[8], ll[8];
#pragma unroll
      for (int t = 0; t < 8; t++) {
        __half h = __float2half_rn(a[t]);
        hh[t] = h;
        ll[t] = __float2half_rn(a[t] - __half2float(h));
      }
      uint32_t off = rowByte + (uint32_t)col * 2;
      *(uint4*)(smc + MSG_AH + off) = *(uint4*)hh;
      *(uint4*)(smc + MSG_AL + off) = *(uint4*)ll;
    }
  }
  CP_WAIT(0);          // B0, B1 landed (per-thread)
  __syncthreads();     // A resident + B visible block-wide

  // ---- mainloop: 8 chunks of k=32, B double-buffered ----
#pragma unroll 1
  for (int kc = 0; kc < 8; kc++) {
    int cur = kc & 1;
    uint32_t bBase = sb + bLaneBase + (uint32_t)cur * MSG_BSTAGE;
#pragma unroll
    for (int ks = 0; ks < 2; ks++) {
      uint32_t a_hi[2][4], a_lo[2][4];
#pragma unroll
      for (int mi = 0; mi < 2; mi++) {
        uint32_t off = (uint32_t)((wm * 32 + mi * 16 + lrow) * 528)
                     + (uint32_t)((kc * 32 + ks * 16 + lcol) * 2);
        ldm4(a_hi[mi], sb + MSG_AH + off);
        ldm4(a_lo[mi], sb + MSG_AL + off);
      }
#pragma unroll
      for (int ni = 0; ni < 8; ni++) {
        uint32_t bf[4];
        ldm4(bf, bBase + (uint32_t)(ks * 32 + ni * 640));
#pragma unroll
        for (int mi = 0; mi < 2; mi++) {
          mma16816(acc[mi][ni], a_hi[mi], bf);       // hi * bh
          mma16816(acc[mi][ni], a_hi[mi], bf + 2);   // hi * bl
          mma16816(acc[mi][ni], a_lo[mi], bf);       // lo * bh
        }
      }
    }
    if (kc < 7) {
      CP_WAIT(0);       // B(kc+1) landed (per-thread)
      __syncthreads();  // all warps done MMA(kc); B(kc+1) visible
      if (kc < 6) cpB(kc + 2, cur);   // safe: stage cur no longer read
    }
  }

  // ---- epilogue: +msg_input, relu, store, scatter ----
#pragma unroll
  for (int mi = 0; mi < 2; mi++) {
    int r0 = bm + wm * 32 + mi * 16 + gid;
    int r1 = r0 + 8;
    bool v0 = r0 < E, v1 = r1 < E;
    int d0 = v0 ? __ldg(edst + r0) : 0;
    int d1 = v1 ? __ldg(edst + r1) : 0;
    const float* MI0 = msg_input + (size_t)r0 * H;
    const float* MI1 = msg_input + (size_t)r1 * H;
    float* MO0 = msg_out + (size_t)r0 * H;
    float* MO1 = msg_out + (size_t)r1 * H;
    float* SN0 = Snext + (size_t)d0 * H;
    float* SN1 = Snext + (size_t)d1 * H;
#pragma unroll
    for (int ni = 0; ni < 8; ni++) {
      int n = wn * 64 + ni * 8 + tig * 2;
      if (v0) {
        float2 m0 = *(const float2*)(MI0 + n);
        float o0 = fmaxf(acc[mi][ni][0] + m0.x, 0.f);
        float o1 = fmaxf(acc[mi][ni][1] + m0.y, 0.f);
        float2 o = {o0, o1};
        *(float2*)(MO0 + n) = o;
        red_add2(SN0 + n, o0, o1);
      }
      if (v1) {
        float2 m1 = *(const float2*)(MI1 + n);
        float o2 = fmaxf(acc[mi][ni][2] + m1.x, 0.f);
        float o3 = fmaxf(acc[mi][ni][3] + m1.y, 0.f);
        float2 o = {o2, o3};
        *(float2*)(MO1 + n) = o;
        red_add2(SN1 + n, o2, o3);
      }
    }
  }
}

// ---------------- output GEMM: permuted A, ldmatrix B fragments --------------
__global__ __launch_bounds__(256, 2) void k_out(
    const float* __restrict__ x, const float* __restrict__ S,
    const __half* __restrict__ Wo_hi, const __half* __restrict__ Wo_lo,
    const float* __restrict__ b_o, float* __restrict__ out,
    int N, int APM)
{
  extern __shared__ __align__(16) char smc[];
  uint32_t sb = smem_u32(smc);
  int tid = threadIdx.x, wid = tid >> 5, lane = tid & 31;
  int wm = wid & 1, wn = wid >> 1;
  int gid = lane >> 2, tig = lane & 3;
  int bm = blockIdx.x * 64;

  int srow = tid >> 2;
  int skq  = (tid & 3) * 8;
  int node = bm + srow;
  bool nv = node < N;
  const float* Xp = x + (size_t)node * AF;
  const float* Sp = S + (size_t)node * H + skq;

  const char* WHp = (const char*)(Wo_hi + (size_t)tid * KO_PAD);
  const char* WLp = (const char*)(Wo_lo + (size_t)tid * KO_PAD);
  uint32_t aStoreOff = (uint32_t)(srow * 80 + skq * 2);
  uint32_t bDstOff   = (uint32_t)(tid * 80);

  int lrow = (lane & 7) + ((lane >> 3) & 1) * 8;
  int lcol = (lane >> 4) * 8;

  int selB = lane >> 3;
  uint32_t bLaneBase = 20480u + (uint32_t)((selB >> 1) * 20480)
                     + (uint32_t)((wn * 64 + (lane & 7)) * 80)
                     + (uint32_t)((selB & 1) * 16);

  float acc[2][8][4];
#pragma unroll
  for (int mi = 0; mi < 2; mi++)
#pragma unroll
    for (int ni = 0; ni < 8; ni++)
#pragma unroll
      for (int q = 0; q < 4; q++) acc[mi][ni][q] = 0.f;

  float ga[8];

  auto cpB = [&](int kc, int buf) {
    const char* sh = WHp + kc * 64;
    const char* sl = WLp + kc * 64;
    uint32_t dh = sb + OFF_BH(buf) + bDstOff;
    uint32_t dl = sb + OFF_BL(buf) + bDstOff;
#pragma unroll
    for (int i = 0; i < 4; i++) CP16(dh + i * 16, sh + i * 16);
#pragma unroll
    for (int i = 0; i < 4; i++) CP16(dl + i * 16, sl + i * 16);
    CP_COMMIT();
  };
  auto gatherA = [&](int kc) {
    if (kc < 8) {
      if (nv) {
        float4 v0 = *(const float4*)(Sp + kc * 32);
        float4 v1 = *(const float4*)(Sp + kc * 32 + 4);
        ga[0] = v0.x; ga[1] = v0.y; ga[2] = v0.z; ga[3] = v0.w;
        ga[4] = v1.x; ga[5] = v1.y; ga[6] = v1.z; ga[7] = v1.w;
      } else {
#pragma unroll
        for (int j = 0; j < 8; j++) ga[j] = 0.f;
      }
    } else {
#pragma unroll
      for (int j = 0; j < 8; j++) {
        int idx = kc * 32 + skq + j - H;
        ga[j] = (nv && idx < AF) ? Xp[idx] : 0.f;
      }
    }
  };
  auto storeA = [&](int buf) {
    __half hh[8], ll[8];
#pragma unroll
    for (int j = 0; j < 8; j++) {
      __half h = __float2half_rn(ga[j]);
      hh[j] = h;
      ll[j] = __float2half_rn(ga[j] - __half2float(h));
    }
    *(uint4*)(smc + OFF_AH(buf) + aStoreOff) = *(uint4*)hh;
    *(uint4*)(smc + OFF_AL(buf) + aStoreOff) = *(uint4*)ll;
  };

  cpB(0, 0);
  gatherA(0);
  cpB(1, 1);
  storeA(0);
  gatherA(1);
  CP_WAIT(1);
  __syncthreads();

#pragma unroll 1
  for (int kc = 0; kc < 10; kc++) {
    int cur = kc & 1;
    uint32_t aH = sb + OFF_AH(cur), aL = sb + OFF_AL(cur);
    uint32_t bBase = sb + bLaneBase + (uint32_t)cur * 40960u;
#pragma unroll
    for (int ks = 0; ks < 2; ks++) {
      uint32_t a_hi[2][4], a_lo[2][4];
#pragma unroll
      for (int mi = 0; mi < 2; mi++) {
        uint32_t off = (uint32_t)((wm * 32 + mi * 16 + lrow) * LDA2 + ks * 16 + lcol) * 2;
        ldm4(a_hi[mi], aH + off);
        ldm4(a_lo[mi], aL + off);
      }
#pragma unroll
      for (int ni = 0; ni < 8; ni++) {
        uint32_t bf[4];
        ldm4(bf, bBase + (uint32_t)(ks * 32 + ni * 640));
#pragma unroll
        for (int mi = 0; mi < 2; mi++) {
          mma16816(acc[mi][ni], a_hi[mi], bf);
          mma16816(acc[mi][ni], a_hi[mi], bf + 2);
          mma16816(acc[mi][ni], a_lo[mi], bf);
        }
      }
    }
    if (kc < 9) storeA(cur ^ 1);
    CP_WAIT(0);
    __syncthreads();
    if (kc < 8) { cpB(kc + 2, cur); gatherA(kc + 2); }
  }

  float inv = 1.f / (float)APM;
#pragma unroll
  for (int mi = 0; mi < 2; mi++) {
    int r0 = bm + wm * 32 + mi * 16 + gid;
    int r1 = r0 + 8;
    bool v0 = r0 < N, v1 = r1 < N;
    int mol0 = v0 ? (r0 / APM) : 0;
    int mol1 = v1 ? (r1 / APM) : 0;
    float* O0 = out + (size_t)mol0 * H;
    float* O1 = out + (size_t)mol1 * H;
#pragma unroll
    for (int ni = 0; ni < 8; ni++) {
      int n = wn * 64 + ni * 8 + tig * 2;
      float2 bo = *(const float2*)(b_o + n);
      if (v0) {
        float o0 = fmaxf(acc[mi][ni][0] + bo.x, 0.f) * inv;
        float o1 = fmaxf(acc[mi][ni][1] + bo.y, 0.f) * inv;
        red_add2(O0 + n, o0, o1);
      }
      if (v1) {
        float o2 = fmaxf(acc[mi][ni][2] + bo.x, 0.f) * inv;
        float o3 = fmaxf(acc[mi][ni][3] + bo.y, 0.f) * inv;
        red_add2(O1 + n, o2, o3);
      }
    }
  }
}

// ---------------- host ---------------------------------------------------------
extern "C" void kernel_launch(void* const* d_in, const int* in_sizes, int n_in,
                              void* d_out, int out_size) {
  const float* x    = (const float*)d_in[0];
  const float* bond = (const float*)d_in[1];
  const float* W_i  = (const float*)d_in[2];
  const float* W_h  = (const float*)d_in[3];
  const float* W_o  = (const float*)d_in[4];
  const float* b_o  = (const float*)d_in[5];
  const int*   esrc = (const int*)d_in[6];
  const int*   edst = (const int*)d_in[7];
  (void)n_in;

  int N   = in_sizes[0] / AF;
  int E   = in_sizes[1] / BF;
  int NM  = out_size / H;
  int APM = N / NM;

  float *msg_input, *msgA, *msgB, *S0, *S1, *WiT;
  __half *WhH, *WhL, *WoH, *WoL;
  cudaGetSymbolAddress((void**)&msg_input, g_msg_input);
  cudaGetSymbolAddress((void**)&msgA, g_msgA);
  cudaGetSymbolAddress((void**)&msgB, g_msgB);
  cudaGetSymbolAddress((void**)&S0, g_S0);
  cudaGetSymbolAddress((void**)&S1, g_S1);
  cudaGetSymbolAddress((void**)&WiT, g_WiT);
  cudaGetSymbolAddress((void**)&WhH, g_Wh_hi);
  cudaGetSymbolAddress((void**)&WhL, g_Wh_lo);
  cudaGetSymbolAddress((void**)&WoH, g_Wo_hi);
  cudaGetSymbolAddress((void**)&WoL, g_Wo_lo);

  cudaFuncSetAttribute(k_msg, cudaFuncAttributeMaxDynamicSharedMemorySize, SMEM_MSG);
  cudaFuncSetAttribute(k_out, cudaFuncAttributeMaxDynamicSharedMemorySize, SMEM_TC);
  size_t smem_init = (size_t)(KI * BM + KI * H) * sizeof(float);
  cudaFuncSetAttribute(k_init, cudaFuncAttributeMaxDynamicSharedMemorySize, (int)smem_init);

  size_t sbytes = (size_t)N * H * sizeof(float);

  k_prep<<<(H * KO_PAD + 255) / 256, 256>>>(WiT, W_i, WhH, WhL, W_h, WoH, WoL, W_o);
  cudaMemsetAsync(S0, 0, sbytes);

  int nblk_i = (E + BM - 1) / BM;
  k_init<<<nblk_i, 256, smem_init>>>(x, bond, esrc, edst, WiT, msg_input, S0, E);

  int nblk_e = (E + 127) / 128;
  float* cur = msg_input;    // iteration 0 gathers rev from msg_input (+relu)
  float* nxt = msgA;
  float* Scur = S0;
  float* Snext = S1;
  for (int it = 0; it < 5; it++) {
    cudaMemsetAsync(Snext, 0, sbytes);
    k_msg<<<nblk_e, 512, SMEM_MSG>>>(Scur, cur, msg_input, WhH, WhL,
                                     esrc, edst, nxt, Snext, E, it == 0 ? 1 : 0);
    cur = nxt;
    nxt = (cur == msgA) ? msgB : msgA;
    float* t = Scur; Scur = Snext; Snext = t;
  }

  cudaMemsetAsync(d_out, 0, (size_t)out_size * sizeof(float));
  int nblk_n = (N + 63) / 64;
  k_out<<<nblk_n, 256, SMEM_TC>>>(x, Scur, WoH, WoL, b_o, (float*)d_out, N, APM);
}

// round 12
// speedup vs baseline: 1.0446x; 1.0446x over previous
#include <cuda_runtime.h>
#include <cuda_fp16.h>
#include <cstdint>
#include <cstddef>

#define H        256
#define AF       39
#define BF       11
#define KI       50
#define KO_REAL  295
#define KO_PAD   320
#define EMAX     380000
#define NMAX     200000
#define BM       64
#define LDA2     40            // 32 k + 8 pad (halves)

// ---- k_msg (BM=128, 512 thr) smem layout ----
#define M_AH(b)    ((b) * 20480)
#define M_AL(b)    ((b) * 20480 + 10240)
#define M_BH(b)    (40960 + (b) * 40960)
#define M_BL(b)    (40960 + (b) * 40960 + 20480)
#define SMEM_MSG   122880

// ---- k_out smem layout (256 thr, BM=64) ----
#define OFF_AH(b)  ((b) * 10240)
#define OFF_AL(b)  ((b) * 10240 + 5120)
#define OFF_BH(b)  (20480 + (b) * 40960)
#define OFF_BL(b)  (20480 + (b) * 40960 + 20480)
#define SMEM_TC    102400

// ---------------- scratch (device globals) ----------------------------------
__device__ float g_msg_input[(size_t)EMAX * H];
__device__ float g_msgA[(size_t)EMAX * H];
__device__ float g_msgB[(size_t)EMAX * H];
__device__ float g_S0[(size_t)NMAX * H];
__device__ float g_S1[(size_t)NMAX * H];
__device__ float g_S2[(size_t)NMAX * H];
__device__ float g_WiT[KI * H];
__device__ __half g_Wh_hi[H * H];
__device__ __half g_Wh_lo[H * H];
__device__ __half g_Wo_hi[H * KO_PAD];
__device__ __half g_Wo_lo[H * KO_PAD];

// ---------------- helpers ----------------------------------------------------
__device__ __forceinline__ void red_add4(float* p, float a, float b, float c, float d) {
  asm volatile("red.global.add.v4.f32 [%0], {%1,%2,%3,%4};"
               :: "l"(p), "f"(a), "f"(b), "f"(c), "f"(d) : "memory");
}
__device__ __forceinline__ void red_add2(float* p, float a, float b) {
  asm volatile("red.global.add.v2.f32 [%0], {%1,%2};"
               :: "l"(p), "f"(a), "f"(b) : "memory");
}
__device__ __forceinline__ uint32_t smem_u32(const void* p) {
  return (uint32_t)__cvta_generic_to_shared(p);
}
__device__ __forceinline__ void ldm4(uint32_t* r, uint32_t addr) {
  asm volatile("ldmatrix.sync.aligned.m8n8.x4.shared.b16 {%0,%1,%2,%3}, [%4];"
               : "=r"(r[0]), "=r"(r[1]), "=r"(r[2]), "=r"(r[3]) : "r"(addr));
}
__device__ __forceinline__ void mma16816(float* c, const uint32_t* a, const uint32_t* b) {
  asm volatile("mma.sync.aligned.m16n8k16.row.col.f32.f16.f16.f32 "
               "{%0,%1,%2,%3}, {%4,%5,%6,%7}, {%8,%9}, {%0,%1,%2,%3};"
               : "+f"(c[0]), "+f"(c[1]), "+f"(c[2]), "+f"(c[3])
               : "r"(a[0]), "r"(a[1]), "r"(a[2]), "r"(a[3]),
                 "r"(b[0]), "r"(b[1]));
}
#define CP16(dst, src) \
  asm volatile("cp.async.cg.shared.global [%0], [%1], 16;" :: "r"(dst), "l"(src))
#define CP_COMMIT() asm volatile("cp.async.commit_group;" ::: "memory")
#define CP_WAIT(n)  asm volatile("cp.async.wait_group %0;" :: "n"(n) : "memory")

// ---------------- fused prep ---------------------------------------------------
// W_o k-permuted: [S(256) | x(39) | pad]
__global__ void k_prep(float* __restrict__ WiT, const float* __restrict__ W_i,
                       __half* __restrict__ WhH, __half* __restrict__ WhL,
                       const float* __restrict__ W_h,
                       __half* __restrict__ WoH, __half* __restrict__ WoL,
                       const float* __restrict__ W_o) {
  int idx = blockIdx.x * 256 + threadIdx.x;
  if (idx < KI * H) {
    int k = idx >> 8, h = idx & (H - 1);
    WiT[idx] = W_i[h * KI + k];
  }
  if (idx < H * H) {
    float v = W_h[idx];
    __half hh = __float2half_rn(v);
    WhH[idx] = hh;
    WhL[idx] = __float2half_rn(v - __half2float(hh));
  }
  if (idx < H * KO_PAD) {
    int n = idx / KO_PAD, k = idx - n * KO_PAD;
    float v = 0.f;
    if (k < H)            v = W_o[n * KO_REAL + AF + k];
    else if (k < KO_REAL) v = W_o[n * KO_REAL + (k - H)];
    __half hh = __float2half_rn(v);
    WoH[idx] = hh;
    WoL[idx] = __float2half_rn(v - __half2float(hh));
  }
}

// ---------------- init (SIMT, K=50) + fused scatter into S0 -------------------
__global__ __launch_bounds__(256) void k_init(
    const float* __restrict__ x, const float* __restrict__ bond,
    const int* __restrict__ esrc, const int* __restrict__ edst,
    const float* __restrict__ WiT,
    float* __restrict__ msg_input, float* __restrict__ S0, int E)
{
  extern __shared__ float smf[];
  float* As = smf;                // [KI][BM]
  float* Bs = smf + KI * BM;      // [KI][H]
  __shared__ int s_src[BM];

  int tid = threadIdx.x;
  int bm  = blockIdx.x * BM;
  if (tid < BM) {
    int e = bm + tid;
    s_src[tid] = (e < E) ? esrc[e] : 0;
  }
  __syncthreads();

  for (int i = tid; i < KI * BM; i += 256) {
    int k = i >> 6, m = i & (BM - 1);
    int e = bm + m;
    float v = 0.f;
    if (e < E) v = (k < AF) ? x[(size_t)s_src[m] * AF + k]
                            : bond[(size_t)e * BF + (k - AF)];
    As[k * BM + m] = v;
  }
  for (int i = tid; i < KI * (H / 4); i += 256) {
    int k = i >> 6;
    int h4 = (i & 63) * 4;
    *(float4*)&Bs[k * H + h4] = *(const float4*)&WiT[k * H + h4];
  }
  __syncthreads();

  int tm = tid >> 5, tn = tid & 31;
  float acc[8][8];
#pragma unroll
  for (int i = 0; i < 8; i++)
#pragma unroll
    for (int j = 0; j < 8; j++) acc[i][j] = 0.f;

  for (int k = 0; k < KI; k++) {
    float a[8], b[8];
    *(float4*)(a)     = *(float4*)&As[k * BM + tm * 8];
    *(float4*)(a + 4) = *(float4*)&As[k * BM + tm * 8 + 4];
    *(float4*)(b)     = *(float4*)&Bs[k * H + tn * 8];
    *(float4*)(b + 4) = *(float4*)&Bs[k * H + tn * 8 + 4];
#pragma unroll
    for (int i = 0; i < 8; i++)
#pragma unroll
      for (int j = 0; j < 8; j++)
        acc[i][j] = fmaf(a[i], b[j], acc[i][j]);
  }

#pragma unroll
  for (int i = 0; i < 8; i++) {
    int e = bm + tm * 8 + i;
    if (e >= E) continue;
    int d = edst[e];
    size_t base = (size_t)e * H + tn * 8;
    float4 o0, o1;
    o0.x = acc[i][0]; o0.y = acc[i][1]; o0.z = acc[i][2]; o0.w = acc[i][3];
    o1.x = acc[i][4]; o1.y = acc[i][5]; o1.z = acc[i][6]; o1.w = acc[i][7];
    *(float4*)(msg_input + base)     = o0;
    *(float4*)(msg_input + base + 4) = o1;
    float* sp = S0 + (size_t)d * H + tn * 8;
    red_add4(sp,     fmaxf(o0.x, 0.f), fmaxf(o0.y, 0.f), fmaxf(o0.z, 0.f), fmaxf(o0.w, 0.f));
    red_add4(sp + 4, fmaxf(o1.x, 0.f), fmaxf(o1.y, 0.f), fmaxf(o1.z, 0.f), fmaxf(o1.w, 0.f));
  }
}

// ---------------- message GEMM: round-10 pipeline + fused tail zeroing -------
// msg_out[e] = relu(msg_input[e] + (S[src[e]] - msg_cur[rev(e)]) @ W_h^T)
__global__ __launch_bounds__(512, 1) void k_msg(
    const float* __restrict__ S, const float* __restrict__ msg_cur,
    const float* __restrict__ msg_input,
    const __half* __restrict__ Wh_hi, const __half* __restrict__ Wh_lo,
    const int* __restrict__ esrc, const int* __restrict__ edst,
    float* __restrict__ msg_out, float* __restrict__ Snext,
    float4* __restrict__ Szero, int NH4, int E, int relu_rev)
{
  extern __shared__ __align__(16) char smc[];
  uint32_t sb = smem_u32(smc);
  int tid = threadIdx.x, wid = tid >> 5, lane = tid & 31;
  int wm = wid & 3, wn = wid >> 2;          // 4 m-warps x 4 n-warps
  int gid = lane >> 2, tig = lane & 3;
  int bm = blockIdx.x * 128;

  int srow = tid >> 2;          // 0..127
  int skq  = (tid & 3) * 8;
  int e = bm + srow;
  bool ev = e < E;
  int eh = E >> 1;
  int sidx = 0, ridx = 0;
  if (ev) { sidx = __ldg(esrc + e); ridx = (e < eh) ? (e + eh) : (e - eh); }
  const float* Sp = S       + (size_t)sidx * H + skq;
  const float* Rp = msg_cur + (size_t)ridx * H + skq;

  // B copy: thread pairs split hi/lo rows (row = tid>>1)
  int bRow  = tid >> 1;
  int bHalf = tid & 1;
  const char* Wsrc = (const char*)((bHalf ? Wh_lo : Wh_hi) + (size_t)bRow * H);
  uint32_t aStoreOff = (uint32_t)(srow * 80 + skq * 2);

  int lrow = (lane & 7) + ((lane >> 3) & 1) * 8;
  int lcol = (lane >> 4) * 8;

  // ldmatrix.x4 B base: lanes 0-7 bh k-lo, 8-15 bh k+8, 16-23 bl k-lo, 24-31 bl k+8
  int selB = lane >> 3;
  uint32_t bLaneBase = 40960u + (uint32_t)((selB >> 1) * 20480)
                     + (uint32_t)((wn * 64 + (lane & 7)) * 80)
                     + (uint32_t)((selB & 1) * 16);

  float acc[2][8][4];
#pragma unroll
  for (int mi = 0; mi < 2; mi++)
#pragma unroll
    for (int ni = 0; ni < 8; ni++)
#pragma unroll
      for (int q = 0; q < 4; q++) acc[mi][ni][q] = 0.f;

  float4 ga0, ga1, gr0, gr1;

  auto cpB = [&](int kc, int buf) {
    const char* s = Wsrc + kc * 64;
    uint32_t d = sb + (bHalf ? M_BL(buf) : M_BH(buf)) + (uint32_t)bRow * 80;
#pragma unroll
    for (int i = 0; i < 4; i++) CP16(d + i * 16, s + i * 16);
    CP_COMMIT();
  };
  auto gatherA = [&](int kc) {
    if (ev) {
      ga0 = *(const float4*)(Sp + kc * 32);
      ga1 = *(const float4*)(Sp + kc * 32 + 4);
      gr0 = *(const float4*)(Rp + kc * 32);
      gr1 = *(const float4*)(Rp + kc * 32 + 4);
      if (relu_rev) {
        gr0.x = fmaxf(gr0.x, 0.f); gr0.y = fmaxf(gr0.y, 0.f);
        gr0.z = fmaxf(gr0.z, 0.f); gr0.w = fmaxf(gr0.w, 0.f);
        gr1.x = fmaxf(gr1.x, 0.f); gr1.y = fmaxf(gr1.y, 0.f);
        gr1.z = fmaxf(gr1.z, 0.f); gr1.w = fmaxf(gr1.w, 0.f);
      }
    } else {
      ga0 = ga1 = gr0 = gr1 = make_float4(0.f, 0.f, 0.f, 0.f);
    }
  };
  auto storeA = [&](int buf) {
    float a[8];
    a[0] = ga0.x - gr0.x; a[1] = ga0.y - gr0.y; a[2] = ga0.z - gr0.z; a[3] = ga0.w - gr0.w;
    a[4] = ga1.x - gr1.x; a[5] = ga1.y - gr1.y; a[6] = ga1.z - gr1.z; a[7] = ga1.w - gr1.w;
    __half hh[8], ll[8];
#pragma unroll
    for (int j = 0; j < 8; j++) {
      __half h = __float2half_rn(a[j]);
      hh[j] = h;
      ll[j] = __float2half_rn(a[j] - __half2float(h));
    }
    *(uint4*)(smc + M_AH(buf) + aStoreOff) = *(uint4*)hh;
    *(uint4*)(smc + M_AL(buf) + aStoreOff) = *(uint4*)ll;
  };

  cpB(0, 0);
  gatherA(0);
  cpB(1, 1);
  storeA(0);
  gatherA(1);
  CP_WAIT(1);
  __syncthreads();

#pragma unroll 1
  for (int kc = 0; kc < 8; kc++) {
    int cur = kc & 1;
    uint32_t aH = sb + M_AH(cur), aL = sb + M_AL(cur);
    uint32_t bBase = sb + bLaneBase + (uint32_t)cur * 40960u;
#pragma unroll
    for (int ks = 0; ks < 2; ks++) {
      uint32_t a_hi[2][4], a_lo[2][4];
#pragma unroll
      for (int mi = 0; mi < 2; mi++) {
        uint32_t off = (uint32_t)((wm * 32 + mi * 16 + lrow) * LDA2 + ks * 16 + lcol) * 2;
        ldm4(a_hi[mi], aH + off);
        ldm4(a_lo[mi], aL + off);
      }
#pragma unroll
      for (int ni = 0; ni < 8; ni++) {
        uint32_t bf[4];
        ldm4(bf, bBase + (uint32_t)(ks * 32 + ni * 640));
#pragma unroll
        for (int mi = 0; mi < 2; mi++) {
          mma16816(acc[mi][ni], a_hi[mi], bf);       // hi * bh
          mma16816(acc[mi][ni], a_hi[mi], bf + 2);   // hi * bl
          mma16816(acc[mi][ni], a_lo[mi], bf);       // lo * bh
        }
      }
    }
    if (kc < 7) storeA(cur ^ 1);
    CP_WAIT(0);
    __syncthreads();
    if (kc < 6) { cpB(kc + 2, cur); gatherA(kc + 2); }
  }

  // epilogue: +msg_input, relu, store, scatter
#pragma unroll
  for (int mi = 0; mi < 2; mi++) {
    int r0 = bm + wm * 32 + mi * 16 + gid;
    int r1 = r0 + 8;
    bool v0 = r0 < E, v1 = r1 < E;
    int d0 = v0 ? __ldg(edst + r0) : 0;
    int d1 = v1 ? __ldg(edst + r1) : 0;
    const float* MI0 = msg_input + (size_t)r0 * H;
    const float* MI1 = msg_input + (size_t)r1 * H;
    float* MO0 = msg_out + (size_t)r0 * H;
    float* MO1 = msg_out + (size_t)r1 * H;
    float* SN0 = Snext + (size_t)d0 * H;
    float* SN1 = Snext + (size_t)d1 * H;
#pragma unroll
    for (int ni = 0; ni < 8; ni++) {
      int n = wn * 64 + ni * 8 + tig * 2;
      if (v0) {
        float2 m0 = *(const float2*)(MI0 + n);
        float o0 = fmaxf(acc[mi][ni][0] + m0.x, 0.f);
        float o1 = fmaxf(acc[mi][ni][1] + m0.y, 0.f);
        float2 o = {o0, o1};
        *(float2*)(MO0 + n) = o;
        red_add2(SN0 + n, o0, o1);
      }
      if (v1) {
        float2 m1 = *(const float2*)(MI1 + n);
        float o2 = fmaxf(acc[mi][ni][2] + m1.x, 0.f);
        float o3 = fmaxf(acc[mi][ni][3] + m1.y, 0.f);
        float2 o = {o2, o3};
        *(float2*)(MO1 + n) = o;
        red_add2(SN1 + n, o2, o3);
      }
    }
  }

  // fused tail zeroing of the S buffer for iteration it+2 (fire-and-forget)
  {
    float4 z = make_float4(0.f, 0.f, 0.f, 0.f);
    int stride = gridDim.x * 512;
    for (int i = blockIdx.x * 512 + tid; i < NH4; i += stride) Szero[i] = z;
  }
}

// ---------------- output GEMM: permuted A, ldmatrix B fragments --------------
__global__ __launch_bounds__(256, 2) void k_out(
    const float* __restrict__ x, const float* __restrict__ S,
    const __half* __restrict__ Wo_hi, const __half* __restrict__ Wo_lo,
    const float* __restrict__ b_o, float* __restrict__ out,
    int N, int APM)
{
  extern __shared__ __align__(16) char smc[];
  uint32_t sb = smem_u32(smc);
  int tid = threadIdx.x, wid = tid >> 5, lane = tid & 31;
  int wm = wid & 1, wn = wid >> 1;
  int gid = lane >> 2, tig = lane & 3;
  int bm = blockIdx.x * 64;

  int srow = tid >> 2;
  int skq  = (tid & 3) * 8;
  int node = bm + srow;
  bool nv = node < N;
  const float* Xp = x + (size_t)node * AF;
  const float* Sp = S + (size_t)node * H + skq;

  const char* WHp = (const char*)(Wo_hi + (size_t)tid * KO_PAD);
  const char* WLp = (const char*)(Wo_lo + (size_t)tid * KO_PAD);
  uint32_t aStoreOff = (uint32_t)(srow * 80 + skq * 2);
  uint32_t bDstOff   = (uint32_t)(tid * 80);

  int lrow = (lane & 7) + ((lane >> 3) & 1) * 8;
  int lcol = (lane >> 4) * 8;

  int selB = lane >> 3;
  uint32_t bLaneBase = 20480u + (uint32_t)((selB >> 1) * 20480)
                     + (uint32_t)((wn * 64 + (lane & 7)) * 80)
                     + (uint32_t)((selB & 1) * 16);

  float acc[2][8][4];
#pragma unroll
  for (int mi = 0; mi < 2; mi++)
#pragma unroll
    for (int ni = 0; ni < 8; ni++)
#pragma unroll
      for (int q = 0; q < 4; q++) acc[mi][ni][q] = 0.f;

  float ga[8];

  auto cpB = [&](int kc, int buf) {
    const char* sh = WHp + kc * 64;
    const char* sl = WLp + kc * 64;
    uint32_t dh = sb + OFF_BH(buf) + bDstOff;
    uint32_t dl = sb + OFF_BL(buf) + bDstOff;
#pragma unroll
    for (int i = 0; i < 4; i++) CP16(dh + i * 16, sh + i * 16);
#pragma unroll
    for (int i = 0; i < 4; i++) CP16(dl + i * 16, sl + i * 16);
    CP_COMMIT();
  };
  auto gatherA = [&](int kc) {
    if (kc < 8) {
      if (nv) {
        float4 v0 = *(const float4*)(Sp + kc * 32);
        float4 v1 = *(const float4*)(Sp + kc * 32 + 4);
        ga[0] = v0.x; ga[1] = v0.y; ga[2] = v0.z; ga[3] = v0.w;
        ga[4] = v1.x; ga[5] = v1.y; ga[6] = v1.z; ga[7] = v1.w;
      } else {
#pragma unroll
        for (int j = 0; j < 8; j++) ga[j] = 0.f;
      }
    } else {
#pragma unroll
      for (int j = 0; j < 8; j++) {
        int idx = kc * 32 + skq + j - H;
        ga[j] = (nv && idx < AF) ? Xp[idx] : 0.f;
      }
    }
  };
  auto storeA = [&](int buf) {
    __half hh[8], ll[8];
#pragma unroll
    for (int j = 0; j < 8; j++) {
      __half h = __float2half_rn(ga[j]);
      hh[j] = h;
      ll[j] = __float2half_rn(ga[j] - __half2float(h));
    }
    *(uint4*)(smc + OFF_AH(buf) + aStoreOff) = *(uint4*)hh;
    *(uint4*)(smc + OFF_AL(buf) + aStoreOff) = *(uint4*)ll;
  };

  cpB(0, 0);
  gatherA(0);
  cpB(1, 1);
  storeA(0);
  gatherA(1);
  CP_WAIT(1);
  __syncthreads();

#pragma unroll 1
  for (int kc = 0; kc < 10; kc++) {
    int cur = kc & 1;
    uint32_t aH = sb + OFF_AH(cur), aL = sb + OFF_AL(cur);
    uint32_t bBase = sb + bLaneBase + (uint32_t)cur * 40960u;
#pragma unroll
    for (int ks = 0; ks < 2; ks++) {
      uint32_t a_hi[2][4], a_lo[2][4];
#pragma unroll
      for (int mi = 0; mi < 2; mi++) {
        uint32_t off = (uint32_t)((wm * 32 + mi * 16 + lrow) * LDA2 + ks * 16 + lcol) * 2;
        ldm4(a_hi[mi], aH + off);
        ldm4(a_lo[mi], aL + off);
      }
#pragma unroll
      for (int ni = 0; ni < 8; ni++) {
        uint32_t bf[4];
        ldm4(bf, bBase + (uint32_t)(ks * 32 + ni * 640));
#pragma unroll
        for (int mi = 0; mi < 2; mi++) {
          mma16816(acc[mi][ni], a_hi[mi], bf);
          mma16816(acc[mi][ni], a_hi[mi], bf + 2);
          mma16816(acc[mi][ni], a_lo[mi], bf);
        }
      }
    }
    if (kc < 9) storeA(cur ^ 1);
    CP_WAIT(0);
    __syncthreads();
    if (kc < 8) { cpB(kc + 2, cur); gatherA(kc + 2); }
  }

  float inv = 1.f / (float)APM;
#pragma unroll
  for (int mi = 0; mi < 2; mi++) {
    int r0 = bm + wm * 32 + mi * 16 + gid;
    int r1 = r0 + 8;
    bool v0 = r0 < N, v1 = r1 < N;
    int mol0 = v0 ? (r0 / APM) : 0;
    int mol1 = v1 ? (r1 / APM) : 0;
    float* O0 = out + (size_t)mol0 * H;
    float* O1 = out + (size_t)mol1 * H;
#pragma unroll
    for (int ni = 0; ni < 8; ni++) {
      int n = wn * 64 + ni * 8 + tig * 2;
      float2 bo = *(const float2*)(b_o + n);
      if (v0) {
        float o0 = fmaxf(acc[mi][ni][0] + bo.x, 0.f) * inv;
        float o1 = fmaxf(acc[mi][ni][1] + bo.y, 0.f) * inv;
        red_add2(O0 + n, o0, o1);
      }
      if (v1) {
        float o2 = fmaxf(acc[mi][ni][2] + bo.x, 0.f) * inv;
        float o3 = fmaxf(acc[mi][ni][3] + bo.y, 0.f) * inv;
        red_add2(O1 + n, o2, o3);
      }
    }
  }
}

// ---------------- host ---------------------------------------------------------
extern "C" void kernel_launch(void* const* d_in, const int* in_sizes, int n_in,
                              void* d_out, int out_size) {
  const float* x    = (const float*)d_in[0];
  const float* bond = (const float*)d_in[1];
  const float* W_i  = (const float*)d_in[2];
  const float* W_h  = (const float*)d_in[3];
  const float* W_o  = (const float*)d_in[4];
  const float* b_o  = (const float*)d_in[5];
  const int*   esrc = (const int*)d_in[6];
  const int*   edst = (const int*)d_in[7];
  (void)n_in;

  int N   = in_sizes[0] / AF;
  int E   = in_sizes[1] / BF;
  int NM  = out_size / H;
  int APM = N / NM;

  float *msg_input, *msgA, *msgB, *WiT;
  float *Sb[3];
  __half *WhH, *WhL, *WoH, *WoL;
  cudaGetSymbolAddress((void**)&msg_input, g_msg_input);
  cudaGetSymbolAddress((void**)&msgA, g_msgA);
  cudaGetSymbolAddress((void**)&msgB, g_msgB);
  cudaGetSymbolAddress((void**)&Sb[0], g_S0);
  cudaGetSymbolAddress((void**)&Sb[1], g_S1);
  cudaGetSymbolAddress((void**)&Sb[2], g_S2);
  cudaGetSymbolAddress((void**)&WiT, g_WiT);
  cudaGetSymbolAddress((void**)&WhH, g_Wh_hi);
  cudaGetSymbolAddress((void**)&WhL, g_Wh_lo);
  cudaGetSymbolAddress((void**)&WoH, g_Wo_hi);
  cudaGetSymbolAddress((void**)&WoL, g_Wo_lo);

  cudaFuncSetAttribute(k_msg, cudaFuncAttributeMaxDynamicSharedMemorySize, SMEM_MSG);
  cudaFuncSetAttribute(k_out, cudaFuncAttributeMaxDynamicSharedMemorySize, SMEM_TC);
  size_t smem_init = (size_t)(KI * BM + KI * H) * sizeof(float);
  cudaFuncSetAttribute(k_init, cudaFuncAttributeMaxDynamicSharedMemorySize, (int)smem_init);

  size_t sbytes = (size_t)N * H * sizeof(float);
  int NH4 = N * (H / 4);

  // hoisted zeroing (overlap-free region, one-time)
  cudaMemsetAsync(d_out, 0, (size_t)out_size * sizeof(float));
  cudaMemsetAsync(Sb[0], 0, sbytes);
  cudaMemsetAsync(Sb[1], 0, sbytes);
  k_prep<<<(H * KO_PAD + 255) / 256, 256>>>(WiT, W_i, WhH, WhL, W_h, WoH, WoL, W_o);

  int nblk_i = (E + BM - 1) / BM;
  k_init<<<nblk_i, 256, smem_init>>>(x, bond, esrc, edst, WiT, msg_input, Sb[0], E);

  int nblk_e = (E + 127) / 128;
  float* cur = msg_input;    // iteration 0 gathers rev from msg_input (+relu)
  float* nxt = msgA;
  for (int it = 0; it < 5; it++) {
    float* Scur  = Sb[it % 3];
    float* Snext = Sb[(it + 1) % 3];
    float* Szero = Sb[(it + 2) % 3];
    k_msg<<<nblk_e, 512, SMEM_MSG>>>(Scur, cur, msg_input, WhH, WhL,
                                     esrc, edst, nxt, Snext,
                                     (float4*)Szero, NH4, E, it == 0 ? 1 : 0);
    cur = nxt;
    nxt = (cur == msgA) ? msgB : msgA;
  }

  int nblk_n = (N + 63) / 64;
  k_out<<<nblk_n, 256, SMEM_TC>>>(x, Sb[5 % 3], WoH, WoL, b_o, (float*)d_out, N, APM);
}

// round 14
// speedup vs baseline: 1.0803x; 1.0341x over previous
#include <cuda_runtime.h>
#include <cuda_fp16.h>
#include <cstdint>
#include <cstddef>

#define H        256
#define AF       39
#define BF       11
#define KI       50
#define KIPAD    64
#define KO_REAL  295
#define KO_PAD   320
#define EMAX     380000
#define NMAX     200000
#define LDA2     40            // 32 k + 8 pad (halves)

// ---- k_msg / k_init (BM=128, 512 thr) smem layout ----
#define M_AH(b)    ((b) * 20480)
#define M_AL(b)    ((b) * 20480 + 10240)
#define M_BH(b)    (40960 + (b) * 40960)
#define M_BL(b)    (40960 + (b) * 40960 + 20480)
#define SMEM_MSG   122880

// ---- k_out smem layout (256 thr, BM=64) ----
#define OFF_AH(b)  ((b) * 10240)
#define OFF_AL(b)  ((b) * 10240 + 5120)
#define OFF_BH(b)  (20480 + (b) * 40960)
#define OFF_BL(b)  (20480 + (b) * 40960 + 20480)
#define SMEM_TC    102400

// ---------------- scratch (device globals) ----------------------------------
__device__ float g_msg_input[(size_t)EMAX * H];
__device__ float g_msgA[(size_t)EMAX * H];
__device__ float g_msgB[(size_t)EMAX * H];
__device__ float g_S0[(size_t)NMAX * H];
__device__ float g_S1[(size_t)NMAX * H];
__device__ __half g_Wi_hi[H * KIPAD];
__device__ __half g_Wi_lo[H * KIPAD];
__device__ __half g_Wh_hi[H * H];
__device__ __half g_Wh_lo[H * H];
__device__ __half g_Wo_hi[H * KO_PAD];
__device__ __half g_Wo_lo[H * KO_PAD];

// ---------------- helpers ----------------------------------------------------
__device__ __forceinline__ void red_add2(float* p, float a, float b) {
  asm volatile("red.global.add.v2.f32 [%0], {%1,%2};"
               :: "l"(p), "f"(a), "f"(b) : "memory");
}
__device__ __forceinline__ uint32_t smem_u32(const void* p) {
  return (uint32_t)__cvta_generic_to_shared(p);
}
__device__ __forceinline__ void ldm4(uint32_t* r, uint32_t addr) {
  asm volatile("ldmatrix.sync.aligned.m8n8.x4.shared.b16 {%0,%1,%2,%3}, [%4];"
               : "=r"(r[0]), "=r"(r[1]), "=r"(r[2]), "=r"(r[3]) : "r"(addr));
}
__device__ __forceinline__ void mma16816(float* c, const uint32_t* a, const uint32_t* b) {
  asm volatile("mma.sync.aligned.m16n8k16.row.col.f32.f16.f16.f32 "
               "{%0,%1,%2,%3}, {%4,%5,%6,%7}, {%8,%9}, {%0,%1,%2,%3};"
               : "+f"(c[0]), "+f"(c[1]), "+f"(c[2]), "+f"(c[3])
               : "r"(a[0]), "r"(a[1]), "r"(a[2]), "r"(a[3]),
                 "r"(b[0]), "r"(b[1]));
}
#define CP16(dst, src) \
  asm volatile("cp.async.cg.shared.global [%0], [%1], 16;" :: "r"(dst), "l"(src))
#define CP_COMMIT() asm volatile("cp.async.commit_group;" ::: "memory")
#define CP_WAIT(n)  asm volatile("cp.async.wait_group %0;" :: "n"(n) : "memory")

// ---------------- fused prep ---------------------------------------------------
// W_i -> hi/lo fp16 [256][64] (k padded); W_h hi/lo; W_o k-permuted [S|x|pad]
__global__ void k_prep(__half* __restrict__ WiH, __half* __restrict__ WiL,
                       const float* __restrict__ W_i,
                       __half* __restrict__ WhH, __half* __restrict__ WhL,
                       const float* __restrict__ W_h,
                       __half* __restrict__ WoH, __half* __restrict__ WoL,
                       const float* __restrict__ W_o) {
  int idx = blockIdx.x * 256 + threadIdx.x;
  if (idx < H * KIPAD) {
    int n = idx >> 6, k = idx & (KIPAD - 1);
    float v = (k < KI) ? W_i[n * KI + k] : 0.f;
    __half hh = __float2half_rn(v);
    WiH[idx] = hh;
    WiL[idx] = __float2half_rn(v - __half2float(hh));
  }
  if (idx < H * H) {
    float v = W_h[idx];
    __half hh = __float2half_rn(v);
    WhH[idx] = hh;
    WhL[idx] = __float2half_rn(v - __half2float(hh));
  }
  if (idx < H * KO_PAD) {
    int n = idx / KO_PAD, k = idx - n * KO_PAD;
    float v = 0.f;
    if (k < H)            v = W_o[n * KO_REAL + AF + k];
    else if (k < KO_REAL) v = W_o[n * KO_REAL + (k - H)];
    __half hh = __float2half_rn(v);
    WoH[idx] = hh;
    WoL[idx] = __float2half_rn(v - __half2float(hh));
  }
}

// ---------------- init: tensor-core fp16x3, K=64 (2 chunks) -------------------
// msg_input[e] = concat(x[src], bond) @ W_i^T  (raw store)
// S0[dst[e]] += relu(msg_input[e])
__global__ __launch_bounds__(512, 1) void k_init_t(
    const float* __restrict__ x, const float* __restrict__ bond,
    const int* __restrict__ esrc, const int* __restrict__ edst,
    const __half* __restrict__ Wi_hi, const __half* __restrict__ Wi_lo,
    float* __restrict__ msg_input, float* __restrict__ S0, int E)
{
  extern __shared__ __align__(16) char smc[];
  uint32_t sb = smem_u32(smc);
  int tid = threadIdx.x, wid = tid >> 5, lane = tid & 31;
  int wm = wid & 3, wn = wid >> 2;
  int gid = lane >> 2, tig = lane & 3;
  int bm = blockIdx.x * 128;

  int srow = tid >> 2;
  int q    = tid & 3;
  int e = bm + srow;
  bool ev = e < E;
  int sidx = ev ? __ldg(esrc + e) : 0;
  const float* Xp = x    + (size_t)sidx * AF;
  const float* Bp = bond + (size_t)e * BF;

  // B copy: thread pairs split hi/lo rows; row = tid>>1, 64B per chunk (4xCP16)
  int bRow  = tid >> 1;
  int bHalf = tid & 1;
  const char* Wsrc = (const char*)((bHalf ? Wi_lo : Wi_hi) + (size_t)bRow * KIPAD);
  uint32_t aStoreOff = (uint32_t)(srow * 80 + q * 16);

  int lrow = (lane & 7) + ((lane >> 3) & 1) * 8;
  int lcol = (lane >> 4) * 8;
  int selB = lane >> 3;
  uint32_t bLaneBase = 40960u + (uint32_t)((selB >> 1) * 20480)
                     + (uint32_t)((wn * 64 + (lane & 7)) * 80)
                     + (uint32_t)((selB & 1) * 16);

  float acc[2][8][4];
#pragma unroll
  for (int mi = 0; mi < 2; mi++)
#pragma unroll
    for (int ni = 0; ni < 8; ni++)
#pragma unroll
      for (int qq = 0; qq < 4; qq++) acc[mi][ni][qq] = 0.f;

  // prologue: both B chunks (full 64B rows), riding under the A gather
  {
    uint32_t d0 = sb + (bHalf ? M_BL(0) : M_BH(0)) + (uint32_t)bRow * 80;
#pragma unroll
    for (int i = 0; i < 4; i++) CP16(d0 + i * 16, Wsrc + i * 16);
    CP_COMMIT();
    uint32_t d1 = sb + (bHalf ? M_BL(1) : M_BH(1)) + (uint32_t)bRow * 80;
#pragma unroll
    for (int i = 0; i < 4; i++) CP16(d1 + i * 16, Wsrc + 64 + i * 16);
    CP_COMMIT();
  }

  // A gather + convert: 2 chunks of 32 k, thread covers k = kc*32 + q*8 .. +7
#pragma unroll
  for (int kc = 0; kc < 2; kc++) {
    float a[8];
#pragma unroll
    for (int j = 0; j < 8; j++) {
      int k = kc * 32 + q * 8 + j;
      float v = 0.f;
      if (ev) {
        if (k < AF)      v = Xp[k];
        else if (k < KI) v = Bp[k - AF];
      }
      a[j] = v;
    }
    __half hh[8], ll[8];
#pragma unroll
    for (int j = 0; j < 8; j++) {
      __half h = __float2half_rn(a[j]);
      hh[j] = h;
      ll[j] = __float2half_rn(a[j] - __half2float(h));
    }
    *(uint4*)(smc + M_AH(kc) + aStoreOff) = *(uint4*)hh;
    *(uint4*)(smc + M_AL(kc) + aStoreOff) = *(uint4*)ll;
  }
  CP_WAIT(0);
  __syncthreads();

  // 2 chunks of MMA
#pragma unroll
  for (int kc = 0; kc < 2; kc++) {
    uint32_t aH = sb + M_AH(kc), aL = sb + M_AL(kc);
    uint32_t bBase = sb + bLaneBase + (uint32_t)kc * 40960u;
#pragma unroll
    for (int ks = 0; ks < 2; ks++) {
      uint32_t a_hi[2][4], a_lo[2][4];
#pragma unroll
      for (int mi = 0; mi < 2; mi++) {
        uint32_t off = (uint32_t)((wm * 32 + mi * 16 + lrow) * LDA2 + ks * 16 + lcol) * 2;
        ldm4(a_hi[mi], aH + off);
        ldm4(a_lo[mi], aL + off);
      }
#pragma unroll
      for (int ni = 0; ni < 8; ni++) {
        uint32_t bf[4];
        ldm4(bf, bBase + (uint32_t)(ks * 32 + ni * 640));
#pragma unroll
        for (int mi = 0; mi < 2; mi++) {
          mma16816(acc[mi][ni], a_hi[mi], bf);
          mma16816(acc[mi][ni], a_hi[mi], bf + 2);
          mma16816(acc[mi][ni], a_lo[mi], bf);
        }
      }
    }
  }

  // epilogue: store raw msg_input, scatter relu into S0
#pragma unroll
  for (int mi = 0; mi < 2; mi++) {
    int r0 = bm + wm * 32 + mi * 16 + gid;
    int r1 = r0 + 8;
    bool v0 = r0 < E, v1 = r1 < E;
    int d0 = v0 ? __ldg(edst + r0) : 0;
    int d1 = v1 ? __ldg(edst + r1) : 0;
    float* MO0 = msg_input + (size_t)r0 * H;
    float* MO1 = msg_input + (size_t)r1 * H;
    float* SN0 = S0 + (size_t)d0 * H;
    float* SN1 = S0 + (size_t)d1 * H;
#pragma unroll
    for (int ni = 0; ni < 8; ni++) {
      int n = wn * 64 + ni * 8 + tig * 2;
      if (v0) {
        float2 o = {acc[mi][ni][0], acc[mi][ni][1]};
        *(float2*)(MO0 + n) = o;
        red_add2(SN0 + n, fmaxf(o.x, 0.f), fmaxf(o.y, 0.f));
      }
      if (v1) {
        float2 o = {acc[mi][ni][2], acc[mi][ni][3]};
        *(float2*)(MO1 + n) = o;
        red_add2(SN1 + n, fmaxf(o.x, 0.f), fmaxf(o.y, 0.f));
      }
    }
  }
}

// ---------------- message GEMM: round-10 (proven 811us) ----------------------
__global__ __launch_bounds__(512, 1) void k_msg(
    const float* __restrict__ S, const float* __restrict__ msg_cur,
    const float* __restrict__ msg_input,
    const __half* __restrict__ Wh_hi, const __half* __restrict__ Wh_lo,
    const int* __restrict__ esrc, const int* __restrict__ edst,
    float* __restrict__ msg_out, float* __restrict__ Snext, int E, int relu_rev)
{
  extern __shared__ __align__(16) char smc[];
  uint32_t sb = smem_u32(smc);
  int tid = threadIdx.x, wid = tid >> 5, lane = tid & 31;
  int wm = wid & 3, wn = wid >> 2;
  int gid = lane >> 2, tig = lane & 3;
  int bm = blockIdx.x * 128;

  int srow = tid >> 2;
  int skq  = (tid & 3) * 8;
  int e = bm + srow;
  bool ev = e < E;
  int eh = E >> 1;
  int sidx = 0, ridx = 0;
  if (ev) { sidx = __ldg(esrc + e); ridx = (e < eh) ? (e + eh) : (e - eh); }
  const float* Sp = S       + (size_t)sidx * H + skq;
  const float* Rp = msg_cur + (size_t)ridx * H + skq;

  int bRow  = tid >> 1;
  int bHalf = tid & 1;
  const char* Wsrc = (const char*)((bHalf ? Wh_lo : Wh_hi) + (size_t)bRow * H);
  uint32_t aStoreOff = (uint32_t)(srow * 80 + skq * 2);

  int lrow = (lane & 7) + ((lane >> 3) & 1) * 8;
  int lcol = (lane >> 4) * 8;
  int selB = lane >> 3;
  uint32_t bLaneBase = 40960u + (uint32_t)((selB >> 1) * 20480)
                     + (uint32_t)((wn * 64 + (lane & 7)) * 80)
                     + (uint32_t)((selB & 1) * 16);

  float acc[2][8][4];
#pragma unroll
  for (int mi = 0; mi < 2; mi++)
#pragma unroll
    for (int ni = 0; ni < 8; ni++)
#pragma unroll
      for (int q = 0; q < 4; q++) acc[mi][ni][q] = 0.f;

  float4 ga0, ga1, gr0, gr1;

  auto cpB = [&](int kc, int buf) {
    const char* s = Wsrc + kc * 64;
    uint32_t d = sb + (bHalf ? M_BL(buf) : M_BH(buf)) + (uint32_t)bRow * 80;
#pragma unroll
    for (int i = 0; i < 4; i++) CP16(d + i * 16, s + i * 16);
    CP_COMMIT();
  };
  auto gatherA = [&](int kc) {
    if (ev) {
      ga0 = *(const float4*)(Sp + kc * 32);
      ga1 = *(const float4*)(Sp + kc * 32 + 4);
      gr0 = *(const float4*)(Rp + kc * 32);
      gr1 = *(const float4*)(Rp + kc * 32 + 4);
      if (relu_rev) {
        gr0.x = fmaxf(gr0.x, 0.f); gr0.y = fmaxf(gr0.y, 0.f);
        gr0.z = fmaxf(gr0.z, 0.f); gr0.w = fmaxf(gr0.w, 0.f);
        gr1.x = fmaxf(gr1.x, 0.f); gr1.y = fmaxf(gr1.y, 0.f);
        gr1.z = fmaxf(gr1.z, 0.f); gr1.w = fmaxf(gr1.w, 0.f);
      }
    } else {
      ga0 = ga1 = gr0 = gr1 = make_float4(0.f, 0.f, 0.f, 0.f);
    }
  };
  auto storeA = [&](int buf) {
    float a[8];
    a[0] = ga0.x - gr0.x; a[1] = ga0.y - gr0.y; a[2] = ga0.z - gr0.z; a[3] = ga0.w - gr0.w;
    a[4] = ga1.x - gr1.x; a[5] = ga1.y - gr1.y; a[6] = ga1.z - gr1.z; a[7] = ga1.w - gr1.w;
    __half hh[8], ll[8];
#pragma unroll
    for (int j = 0; j < 8; j++) {
      __half h = __float2half_rn(a[j]);
      hh[j] = h;
      ll[j] = __float2half_rn(a[j] - __half2float(h));
    }
    *(uint4*)(smc + M_AH(buf) + aStoreOff) = *(uint4*)hh;
    *(uint4*)(smc + M_AL(buf) + aStoreOff) = *(uint4*)ll;
  };

  cpB(0, 0);
  gatherA(0);
  cpB(1, 1);
  storeA(0);
  gatherA(1);
  CP_WAIT(1);
  __syncthreads();

#pragma unroll 1
  for (int kc = 0; kc < 8; kc++) {
    int cur = kc & 1;
    uint32_t aH = sb + M_AH(cur), aL = sb + M_AL(cur);
    uint32_t bBase = sb + bLaneBase + (uint32_t)cur * 40960u;
#pragma unroll
    for (int ks = 0; ks < 2; ks++) {
      uint32_t a_hi[2][4], a_lo[2][4];
#pragma unroll
      for (int mi = 0; mi < 2; mi++) {
        uint32_t off = (uint32_t)((wm * 32 + mi * 16 + lrow) * LDA2 + ks * 16 + lcol) * 2;
        ldm4(a_hi[mi], aH + off);
        ldm4(a_lo[mi], aL + off);
      }
#pragma unroll
      for (int ni = 0; ni < 8; ni++) {
        uint32_t bf[4];
        ldm4(bf, bBase + (uint32_t)(ks * 32 + ni * 640));
#pragma unroll
        for (int mi = 0; mi < 2; mi++) {
          mma16816(acc[mi][ni], a_hi[mi], bf);
          mma16816(acc[mi][ni], a_hi[mi], bf + 2);
          mma16816(acc[mi][ni], a_lo[mi], bf);
        }
      }
    }
    if (kc < 7) storeA(cur ^ 1);
    CP_WAIT(0);
    __syncthreads();
    if (kc < 6) { cpB(kc + 2, cur); gatherA(kc + 2); }
  }

#pragma unroll
  for (int mi = 0; mi < 2; mi++) {
    int r0 = bm + wm * 32 + mi * 16 + gid;
    int r1 = r0 + 8;
    bool v0 = r0 < E, v1 = r1 < E;
    int d0 = v0 ? __ldg(edst + r0) : 0;
    int d1 = v1 ? __ldg(edst + r1) : 0;
    const float* MI0 = msg_input + (size_t)r0 * H;
    const float* MI1 = msg_input + (size_t)r1 * H;
    float* MO0 = msg_out + (size_t)r0 * H;
    float* MO1 = msg_out + (size_t)r1 * H;
    float* SN0 = Snext + (size_t)d0 * H;
    float* SN1 = Snext + (size_t)d1 * H;
#pragma unroll
    for (int ni = 0; ni < 8; ni++) {
      int n = wn * 64 + ni * 8 + tig * 2;
      if (v0) {
        float2 m0 = *(const float2*)(MI0 + n);
        float o0 = fmaxf(acc[mi][ni][0] + m0.x, 0.f);
        float o1 = fmaxf(acc[mi][ni][1] + m0.y, 0.f);
        float2 o = {o0, o1};
        *(float2*)(MO0 + n) = o;
        red_add2(SN0 + n, o0, o1);
      }
      if (v1) {
        float2 m1 = *(const float2*)(MI1 + n);
        float o2 = fmaxf(acc[mi][ni][2] + m1.x, 0.f);
        float o3 = fmaxf(acc[mi][ni][3] + m1.y, 0.f);
        float2 o = {o2, o3};
        *(float2*)(MO1 + n) = o;
        red_add2(SN1 + n, o2, o3);
      }
    }
  }
}

// ---------------- output GEMM: permuted A, ldmatrix B fragments --------------
__global__ __launch_bounds__(256, 2) void k_out(
    const float* __restrict__ x, const float* __restrict__ S,
    const __half* __restrict__ Wo_hi, const __half* __restrict__ Wo_lo,
    const float* __restrict__ b_o, float* __restrict__ out,
    int N, int APM)
{
  extern __shared__ __align__(16) char smc[];
  uint32_t sb = smem_u32(smc);
  int tid = threadIdx.x, wid = tid >> 5, lane = tid & 31;
  int wm = wid & 1, wn = wid >> 1;
  int gid = lane >> 2, tig = lane & 3;
  int bm = blockIdx.x * 64;

  int srow = tid >> 2;
  int skq  = (tid & 3) * 8;
  int node = bm + srow;
  bool nv = node < N;
  const float* Xp = x + (size_t)node * AF;
  const float* Sp = S + (size_t)node * H + skq;

  const char* WHp = (const char*)(Wo_hi + (size_t)tid * KO_PAD);
  const char* WLp = (const char*)(Wo_lo + (size_t)tid * KO_PAD);
  uint32_t aStoreOff = (uint32_t)(srow * 80 + skq * 2);
  uint32_t bDstOff   = (uint32_t)(tid * 80);

  int lrow = (lane & 7) + ((lane >> 3) & 1) * 8;
  int lcol = (lane >> 4) * 8;
  int selB = lane >> 3;
  uint32_t bLaneBase = 20480u + (uint32_t)((selB >> 1) * 20480)
                     + (uint32_t)((wn * 64 + (lane & 7)) * 80)
                     + (uint32_t)((selB & 1) * 16);

  float acc[2][8][4];
#pragma unroll
  for (int mi = 0; mi < 2; mi++)
#pragma unroll
    for (int ni = 0; ni < 8; ni++)
#pragma unroll
      for (int q = 0; q < 4; q++) acc[mi][ni][q] = 0.f;

  float ga[8];

  auto cpB = [&](int kc, int buf) {
    const char* sh = WHp + kc * 64;
    const char* sl = WLp + kc * 64;
    uint32_t dh = sb + OFF_BH(buf) + bDstOff;
    uint32_t dl = sb + OFF_BL(buf) + bDstOff;
#pragma unroll
    for (int i = 0; i < 4; i++) CP16(dh + i * 16, sh + i * 16);
#pragma unroll
    for (int i = 0; i < 4; i++) CP16(dl + i * 16, sl + i * 16);
    CP_COMMIT();
  };
  auto gatherA = [&](int kc) {
    if (kc < 8) {
      if (nv) {
        float4 v0 = *(const float4*)(Sp + kc * 32);
        float4 v1 = *(const float4*)(Sp + kc * 32 + 4);
        ga[0] = v0.x; ga[1] = v0.y; ga[2] = v0.z; ga[3] = v0.w;
        ga[4] = v1.x; ga[5] = v1.y; ga[6] = v1.z; ga[7] = v1.w;
      } else {
#pragma unroll
        for (int j = 0; j < 8; j++) ga[j] = 0.f;
      }
    } else {
#pragma unroll
      for (int j = 0; j < 8; j++) {
        int idx = kc * 32 + skq + j - H;
        ga[j] = (nv && idx < AF) ? Xp[idx] : 0.f;
      }
    }
  };
  auto storeA = [&](int buf) {
    __half hh[8], ll[8];
#pragma unroll
    for (int j = 0; j < 8; j++) {
      __half h = __float2half_rn(ga[j]);
      hh[j] = h;
      ll[j] = __float2half_rn(ga[j] - __half2float(h));
    }
    *(uint4*)(smc + OFF_AH(buf) + aStoreOff) = *(uint4*)hh;
    *(uint4*)(smc + OFF_AL(buf) + aStoreOff) = *(uint4*)ll;
  };

  cpB(0, 0);
  gatherA(0);
  cpB(1, 1);
  storeA(0);
  gatherA(1);
  CP_WAIT(1);
  __syncthreads();

#pragma unroll 1
  for (int kc = 0; kc < 10; kc++) {
    int cur = kc & 1;
    uint32_t aH = sb + OFF_AH(cur), aL = sb + OFF_AL(cur);
    uint32_t bBase = sb + bLaneBase + (uint32_t)cur * 40960u;
#pragma unroll
    for (int ks = 0; ks < 2; ks++) {
      uint32_t a_hi[2][4], a_lo[2][4];
#pragma unroll
      for (int mi = 0; mi < 2; mi++) {
        uint32_t off = (uint32_t)((wm * 32 + mi * 16 + lrow) * LDA2 + ks * 16 + lcol) * 2;
        ldm4(a_hi[mi], aH + off);
        ldm4(a_lo[mi], aL + off);
      }
#pragma unroll
      for (int ni = 0; ni < 8; ni++) {
        uint32_t bf[4];
        ldm4(bf, bBase + (uint32_t)(ks * 32 + ni * 640));
#pragma unroll
        for (int mi = 0; mi < 2; mi++) {
          mma16816(acc[mi][ni], a_hi[mi], bf);
          mma16816(acc[mi][ni], a_hi[mi], bf + 2);
          mma16816(acc[mi][ni], a_lo[mi], bf);
        }
      }
    }
    if (kc < 9) storeA(cur ^ 1);
    CP_WAIT(0);
    __syncthreads();
    if (kc < 8) { cpB(kc + 2, cur); gatherA(kc + 2); }
  }

  float inv = 1.f / (float)APM;
#pragma unroll
  for (int mi = 0; mi < 2; mi++) {
    int r0 = bm + wm * 32 + mi * 16 + gid;
    int r1 = r0 + 8;
    bool v0 = r0 < N, v1 = r1 < N;
    int mol0 = v0 ? (r0 / APM) : 0;
    int mol1 = v1 ? (r1 / APM) : 0;
    float* O0 = out + (size_t)mol0 * H;
    float* O1 = out + (size_t)mol1 * H;
#pragma unroll
    for (int ni = 0; ni < 8; ni++) {
      int n = wn * 64 + ni * 8 + tig * 2;
      float2 bo = *(const float2*)(b_o + n);
      if (v0) {
        float o0 = fmaxf(acc[mi][ni][0] + bo.x, 0.f) * inv;
        float o1 = fmaxf(acc[mi][ni][1] + bo.y, 0.f) * inv;
        red_add2(O0 + n, o0, o1);
      }
      if (v1) {
        float o2 = fmaxf(acc[mi][ni][2] + bo.x, 0.f) * inv;
        float o3 = fmaxf(acc[mi][ni][3] + bo.y, 0.f) * inv;
        red_add2(O1 + n, o2, o3);
      }
    }
  }
}

// ---------------- host ---------------------------------------------------------
extern "C" void kernel_launch(void* const* d_in, const int* in_sizes, int n_in,
                              void* d_out, int out_size) {
  const float* x    = (const float*)d_in[0];
  const float* bond = (const float*)d_in[1];
  const float* W_i  = (const float*)d_in[2];
  const float* W_h  = (const float*)d_in[3];
  const float* W_o  = (const float*)d_in[4];
  const float* b_o  = (const float*)d_in[5];
  const int*   esrc = (const int*)d_in[6];
  const int*   edst = (const int*)d_in[7];
  (void)n_in;

  int N   = in_sizes[0] / AF;
  int E   = in_sizes[1] / BF;
  int NM  = out_size / H;
  int APM = N / NM;

  float *msg_input, *msgA, *msgB, *S0, *S1;
  __half *WiH, *WiL, *WhH, *WhL, *WoH, *WoL;
  cudaGetSymbolAddress((void**)&msg_input, g_msg_input);
  cudaGetSymbolAddress((void**)&msgA, g_msgA);
  cudaGetSymbolAddress((void**)&msgB, g_msgB);
  cudaGetSymbolAddress((void**)&S0, g_S0);
  cudaGetSymbolAddress((void**)&S1, g_S1);
  cudaGetSymbolAddress((void**)&WiH, g_Wi_hi);
  cudaGetSymbolAddress((void**)&WiL, g_Wi_lo);
  cudaGetSymbolAddress((void**)&WhH, g_Wh_hi);
  cudaGetSymbolAddress((void**)&WhL, g_Wh_lo);
  cudaGetSymbolAddress((void**)&WoH, g_Wo_hi);
  cudaGetSymbolAddress((void**)&WoL, g_Wo_lo);

  cudaFuncSetAttribute(k_init_t, cudaFuncAttributeMaxDynamicSharedMemorySize, SMEM_MSG);
  cudaFuncSetAttribute(k_msg, cudaFuncAttributeMaxDynamicSharedMemorySize, SMEM_MSG);
  cudaFuncSetAttribute(k_out, cudaFuncAttributeMaxDynamicSharedMemorySize, SMEM_TC);

  size_t sbytes = (size_t)N * H * sizeof(float);

  cudaMemsetAsync(d_out, 0, (size_t)out_size * sizeof(float));
  k_prep<<<(H * KO_PAD + 255) / 256, 256>>>(WiH, WiL, W_i, WhH, WhL, W_h, WoH, WoL, W_o);
  cudaMemsetAsync(S0, 0, sbytes);

  int nblk_e = (E + 127) / 128;
  k_init_t<<<nblk_e, 512, SMEM_MSG>>>(x, bond, esrc, edst, WiH, WiL, msg_input, S0, E);

  float* cur = msg_input;    // iteration 0 gathers rev from msg_input (+relu)
  float* nxt = msgA;
  float* Scur = S0;
  float* Snext = S1;
  for (int it = 0; it < 5; it++) {
    cudaMemsetAsync(Snext, 0, sbytes);
    k_msg<<<nblk_e, 512, SMEM_MSG>>>(Scur, cur, msg_input, WhH, WhL,
                                     esrc, edst, nxt, Snext, E, it == 0 ? 1 : 0);
    cur = nxt;
    nxt = (cur == msgA) ? msgB : msgA;
    float* t = Scur; Scur = Snext; Snext = t;
  }

  int nblk_n = (N + 63) / 64;
  k_out<<<nblk_n, 256, SMEM_TC>>>(x, Scur, WoH, WoL, b_o, (float*)d_out, N, APM);
}

// round 15
// speedup vs baseline: 1.0905x; 1.0095x over previous
#include <cuda_runtime.h>
#include <cuda_fp16.h>
#include <cstdint>
#include <cstddef>

#define H        256
#define AF       39
#define BF       11
#define KI       50
#define KIPAD    64
#define KO_REAL  295
#define KO_PAD   320
#define EMAX     380000
#define NMAX     200000
#define LDA2     40            // 32 k + 8 pad (halves)

// ---- shared smem layout for all BM=128 / 512-thr kernels ----
#define M_AH(b)    ((b) * 20480)
#define M_AL(b)    ((b) * 20480 + 10240)
#define M_BH(b)    (40960 + (b) * 40960)
#define M_BL(b)    (40960 + (b) * 40960 + 20480)
#define SMEM_MSG   122880

// ---------------- scratch (device globals) ----------------------------------
__device__ float g_msg_input[(size_t)EMAX * H];
__device__ float g_msgA[(size_t)EMAX * H];
__device__ float g_msgB[(size_t)EMAX * H];
__device__ float g_S0[(size_t)NMAX * H];
__device__ float g_S1[(size_t)NMAX * H];
__device__ __half g_Wi_hi[H * KIPAD];
__device__ __half g_Wi_lo[H * KIPAD];
__device__ __half g_Wh_hi[H * H];
__device__ __half g_Wh_lo[H * H];
__device__ __half g_Wo_hi[H * KO_PAD];
__device__ __half g_Wo_lo[H * KO_PAD];

// ---------------- helpers ----------------------------------------------------
__device__ __forceinline__ void red_add2(float* p, float a, float b) {
  asm volatile("red.global.add.v2.f32 [%0], {%1,%2};"
               :: "l"(p), "f"(a), "f"(b) : "memory");
}
__device__ __forceinline__ uint32_t smem_u32(const void* p) {
  return (uint32_t)__cvta_generic_to_shared(p);
}
__device__ __forceinline__ void ldm4(uint32_t* r, uint32_t addr) {
  asm volatile("ldmatrix.sync.aligned.m8n8.x4.shared.b16 {%0,%1,%2,%3}, [%4];"
               : "=r"(r[0]), "=r"(r[1]), "=r"(r[2]), "=r"(r[3]) : "r"(addr));
}
__device__ __forceinline__ void mma16816(float* c, const uint32_t* a, const uint32_t* b) {
  asm volatile("mma.sync.aligned.m16n8k16.row.col.f32.f16.f16.f32 "
               "{%0,%1,%2,%3}, {%4,%5,%6,%7}, {%8,%9}, {%0,%1,%2,%3};"
               : "+f"(c[0]), "+f"(c[1]), "+f"(c[2]), "+f"(c[3])
               : "r"(a[0]), "r"(a[1]), "r"(a[2]), "r"(a[3]),
                 "r"(b[0]), "r"(b[1]));
}
#define CP16(dst, src) \
  asm volatile("cp.async.cg.shared.global [%0], [%1], 16;" :: "r"(dst), "l"(src))
#define CP_COMMIT() asm volatile("cp.async.commit_group;" ::: "memory")
#define CP_WAIT(n)  asm volatile("cp.async.wait_group %0;" :: "n"(n) : "memory")

// ---------------- fused prep ---------------------------------------------------
// W_i -> hi/lo fp16 [256][64] (k padded); W_h hi/lo; W_o k-permuted [S|x|pad]
__global__ void k_prep(__half* __restrict__ WiH, __half* __restrict__ WiL,
                       const float* __restrict__ W_i,
                       __half* __restrict__ WhH, __half* __restrict__ WhL,
                       const float* __restrict__ W_h,
                       __half* __restrict__ WoH, __half* __restrict__ WoL,
                       const float* __restrict__ W_o) {
  int idx = blockIdx.x * 256 + threadIdx.x;
  if (idx < H * KIPAD) {
    int n = idx >> 6, k = idx & (KIPAD - 1);
    float v = (k < KI) ? W_i[n * KI + k] : 0.f;
    __half hh = __float2half_rn(v);
    WiH[idx] = hh;
    WiL[idx] = __float2half_rn(v - __half2float(hh));
  }
  if (idx < H * H) {
    float v = W_h[idx];
    __half hh = __float2half_rn(v);
    WhH[idx] = hh;
    WhL[idx] = __float2half_rn(v - __half2float(hh));
  }
  if (idx < H * KO_PAD) {
    int n = idx / KO_PAD, k = idx - n * KO_PAD;
    float v = 0.f;
    if (k < H)            v = W_o[n * KO_REAL + AF + k];
    else if (k < KO_REAL) v = W_o[n * KO_REAL + (k - H)];
    __half hh = __float2half_rn(v);
    WoH[idx] = hh;
    WoL[idx] = __float2half_rn(v - __half2float(hh));
  }
}

// ---------------- init: tensor-core fp16x3, K=64 (2 chunks) -------------------
__global__ __launch_bounds__(512, 1) void k_init_t(
    const float* __restrict__ x, const float* __restrict__ bond,
    const int* __restrict__ esrc, const int* __restrict__ edst,
    const __half* __restrict__ Wi_hi, const __half* __restrict__ Wi_lo,
    float* __restrict__ msg_input, float* __restrict__ S0, int E)
{
  extern __shared__ __align__(16) char smc[];
  uint32_t sb = smem_u32(smc);
  int tid = threadIdx.x, wid = tid >> 5, lane = tid & 31;
  int wm = wid & 3, wn = wid >> 2;
  int gid = lane >> 2, tig = lane & 3;
  int bm = blockIdx.x * 128;

  int srow = tid >> 2;
  int q    = tid & 3;
  int e = bm + srow;
  bool ev = e < E;
  int sidx = ev ? __ldg(esrc + e) : 0;
  const float* Xp = x    + (size_t)sidx * AF;
  const float* Bp = bond + (size_t)e * BF;

  int bRow  = tid >> 1;
  int bHalf = tid & 1;
  const char* Wsrc = (const char*)((bHalf ? Wi_lo : Wi_hi) + (size_t)bRow * KIPAD);
  uint32_t aStoreOff = (uint32_t)(srow * 80 + q * 16);

  int lrow = (lane & 7) + ((lane >> 3) & 1) * 8;
  int lcol = (lane >> 4) * 8;
  int selB = lane >> 3;
  uint32_t bLaneBase = 40960u + (uint32_t)((selB >> 1) * 20480)
                     + (uint32_t)((wn * 64 + (lane & 7)) * 80)
                     + (uint32_t)((selB & 1) * 16);

  float acc[2][8][4];
#pragma unroll
  for (int mi = 0; mi < 2; mi++)
#pragma unroll
    for (int ni = 0; ni < 8; ni++)
#pragma unroll
      for (int qq = 0; qq < 4; qq++) acc[mi][ni][qq] = 0.f;

  {
    uint32_t d0 = sb + (bHalf ? M_BL(0) : M_BH(0)) + (uint32_t)bRow * 80;
#pragma unroll
    for (int i = 0; i < 4; i++) CP16(d0 + i * 16, Wsrc + i * 16);
    CP_COMMIT();
    uint32_t d1 = sb + (bHalf ? M_BL(1) : M_BH(1)) + (uint32_t)bRow * 80;
#pragma unroll
    for (int i = 0; i < 4; i++) CP16(d1 + i * 16, Wsrc + 64 + i * 16);
    CP_COMMIT();
  }

#pragma unroll
  for (int kc = 0; kc < 2; kc++) {
    float a[8];
#pragma unroll
    for (int j = 0; j < 8; j++) {
      int k = kc * 32 + q * 8 + j;
      float v = 0.f;
      if (ev) {
        if (k < AF)      v = Xp[k];
        else if (k < KI) v = Bp[k - AF];
      }
      a[j] = v;
    }
    __half hh[8], ll[8];
#pragma unroll
    for (int j = 0; j < 8; j++) {
      __half h = __float2half_rn(a[j]);
      hh[j] = h;
      ll[j] = __float2half_rn(a[j] - __half2float(h));
    }
    *(uint4*)(smc + M_AH(kc) + aStoreOff) = *(uint4*)hh;
    *(uint4*)(smc + M_AL(kc) + aStoreOff) = *(uint4*)ll;
  }
  CP_WAIT(0);
  __syncthreads();

#pragma unroll
  for (int kc = 0; kc < 2; kc++) {
    uint32_t aH = sb + M_AH(kc), aL = sb + M_AL(kc);
    uint32_t bBase = sb + bLaneBase + (uint32_t)kc * 40960u;
#pragma unroll
    for (int ks = 0; ks < 2; ks++) {
      uint32_t a_hi[2][4], a_lo[2][4];
#pragma unroll
      for (int mi = 0; mi < 2; mi++) {
        uint32_t off = (uint32_t)((wm * 32 + mi * 16 + lrow) * LDA2 + ks * 16 + lcol) * 2;
        ldm4(a_hi[mi], aH + off);
        ldm4(a_lo[mi], aL + off);
      }
#pragma unroll
      for (int ni = 0; ni < 8; ni++) {
        uint32_t bf[4];
        ldm4(bf, bBase + (uint32_t)(ks * 32 + ni * 640));
#pragma unroll
        for (int mi = 0; mi < 2; mi++) {
          mma16816(acc[mi][ni], a_hi[mi], bf);
          mma16816(acc[mi][ni], a_hi[mi], bf + 2);
          mma16816(acc[mi][ni], a_lo[mi], bf);
        }
      }
    }
  }

#pragma unroll
  for (int mi = 0; mi < 2; mi++) {
    int r0 = bm + wm * 32 + mi * 16 + gid;
    int r1 = r0 + 8;
    bool v0 = r0 < E, v1 = r1 < E;
    int d0 = v0 ? __ldg(edst + r0) : 0;
    int d1 = v1 ? __ldg(edst + r1) : 0;
    float* MO0 = msg_input + (size_t)r0 * H;
    float* MO1 = msg_input + (size_t)r1 * H;
    float* SN0 = S0 + (size_t)d0 * H;
    float* SN1 = S0 + (size_t)d1 * H;
#pragma unroll
    for (int ni = 0; ni < 8; ni++) {
      int n = wn * 64 + ni * 8 + tig * 2;
      if (v0) {
        float2 o = {acc[mi][ni][0], acc[mi][ni][1]};
        *(float2*)(MO0 + n) = o;
        red_add2(SN0 + n, fmaxf(o.x, 0.f), fmaxf(o.y, 0.f));
      }
      if (v1) {
        float2 o = {acc[mi][ni][2], acc[mi][ni][3]};
        *(float2*)(MO1 + n) = o;
        red_add2(SN1 + n, fmaxf(o.x, 0.f), fmaxf(o.y, 0.f));
      }
    }
  }
}

// ---------------- message GEMM: round-10 (proven 811us) ----------------------
__global__ __launch_bounds__(512, 1) void k_msg(
    const float* __restrict__ S, const float* __restrict__ msg_cur,
    const float* __restrict__ msg_input,
    const __half* __restrict__ Wh_hi, const __half* __restrict__ Wh_lo,
    const int* __restrict__ esrc, const int* __restrict__ edst,
    float* __restrict__ msg_out, float* __restrict__ Snext, int E, int relu_rev)
{
  extern __shared__ __align__(16) char smc[];
  uint32_t sb = smem_u32(smc);
  int tid = threadIdx.x, wid = tid >> 5, lane = tid & 31;
  int wm = wid & 3, wn = wid >> 2;
  int gid = lane >> 2, tig = lane & 3;
  int bm = blockIdx.x * 128;

  int srow = tid >> 2;
  int skq  = (tid & 3) * 8;
  int e = bm + srow;
  bool ev = e < E;
  int eh = E >> 1;
  int sidx = 0, ridx = 0;
  if (ev) { sidx = __ldg(esrc + e); ridx = (e < eh) ? (e + eh) : (e - eh); }
  const float* Sp = S       + (size_t)sidx * H + skq;
  const float* Rp = msg_cur + (size_t)ridx * H + skq;

  int bRow  = tid >> 1;
  int bHalf = tid & 1;
  const char* Wsrc = (const char*)((bHalf ? Wh_lo : Wh_hi) + (size_t)bRow * H);
  uint32_t aStoreOff = (uint32_t)(srow * 80 + skq * 2);

  int lrow = (lane & 7) + ((lane >> 3) & 1) * 8;
  int lcol = (lane >> 4) * 8;
  int selB = lane >> 3;
  uint32_t bLaneBase = 40960u + (uint32_t)((selB >> 1) * 20480)
                     + (uint32_t)((wn * 64 + (lane & 7)) * 80)
                     + (uint32_t)((selB & 1) * 16);

  float acc[2][8][4];
#pragma unroll
  for (int mi = 0; mi < 2; mi++)
#pragma unroll
    for (int ni = 0; ni < 8; ni++)
#pragma unroll
      for (int q = 0; q < 4; q++) acc[mi][ni][q] = 0.f;

  float4 ga0, ga1, gr0, gr1;

  auto cpB = [&](int kc, int buf) {
    const char* s = Wsrc + kc * 64;
    uint32_t d = sb + (bHalf ? M_BL(buf) : M_BH(buf)) + (uint32_t)bRow * 80;
#pragma unroll
    for (int i = 0; i < 4; i++) CP16(d + i * 16, s + i * 16);
    CP_COMMIT();
  };
  auto gatherA = [&](int kc) {
    if (ev) {
      ga0 = *(const float4*)(Sp + kc * 32);
      ga1 = *(const float4*)(Sp + kc * 32 + 4);
      gr0 = *(const float4*)(Rp + kc * 32);
      gr1 = *(const float4*)(Rp + kc * 32 + 4);
      if (relu_rev) {
        gr0.x = fmaxf(gr0.x, 0.f); gr0.y = fmaxf(gr0.y, 0.f);
        gr0.z = fmaxf(gr0.z, 0.f); gr0.w = fmaxf(gr0.w, 0.f);
        gr1.x = fmaxf(gr1.x, 0.f); gr1.y = fmaxf(gr1.y, 0.f);
        gr1.z = fmaxf(gr1.z, 0.f); gr1.w = fmaxf(gr1.w, 0.f);
      }
    } else {
      ga0 = ga1 = gr0 = gr1 = make_float4(0.f, 0.f, 0.f, 0.f);
    }
  };
  auto storeA = [&](int buf) {
    float a[8];
    a[0] = ga0.x - gr0.x; a[1] = ga0.y - gr0.y; a[2] = ga0.z - gr0.z; a[3] = ga0.w - gr0.w;
    a[4] = ga1.x - gr1.x; a[5] = ga1.y - gr1.y; a[6] = ga1.z - gr1.z; a[7] = ga1.w - gr1.w;
    __half hh[8], ll[8];
#pragma unroll
    for (int j = 0; j < 8; j++) {
      __half h = __float2half_rn(a[j]);
      hh[j] = h;
      ll[j] = __float2half_rn(a[j] - __half2float(h));
    }
    *(uint4*)(smc + M_AH(buf) + aStoreOff) = *(uint4*)hh;
    *(uint4*)(smc + M_AL(buf) + aStoreOff) = *(uint4*)ll;
  };

  cpB(0, 0);
  gatherA(0);
  cpB(1, 1);
  storeA(0);
  gatherA(1);
  CP_WAIT(1);
  __syncthreads();

#pragma unroll 1
  for (int kc = 0; kc < 8; kc++) {
    int cur = kc & 1;
    uint32_t aH = sb + M_AH(cur), aL = sb + M_AL(cur);
    uint32_t bBase = sb + bLaneBase + (uint32_t)cur * 40960u;
#pragma unroll
    for (int ks = 0; ks < 2; ks++) {
      uint32_t a_hi[2][4], a_lo[2][4];
#pragma unroll
      for (int mi = 0; mi < 2; mi++) {
        uint32_t off = (uint32_t)((wm * 32 + mi * 16 + lrow) * LDA2 + ks * 16 + lcol) * 2;
        ldm4(a_hi[mi], aH + off);
        ldm4(a_lo[mi], aL + off);
      }
#pragma unroll
      for (int ni = 0; ni < 8; ni++) {
        uint32_t bf[4];
        ldm4(bf, bBase + (uint32_t)(ks * 32 + ni * 640));
#pragma unroll
        for (int mi = 0; mi < 2; mi++) {
          mma16816(acc[mi][ni], a_hi[mi], bf);
          mma16816(acc[mi][ni], a_hi[mi], bf + 2);
          mma16816(acc[mi][ni], a_lo[mi], bf);
        }
      }
    }
    if (kc < 7) storeA(cur ^ 1);
    CP_WAIT(0);
    __syncthreads();
    if (kc < 6) { cpB(kc + 2, cur); gatherA(kc + 2); }
  }

#pragma unroll
  for (int mi = 0; mi < 2; mi++) {
    int r0 = bm + wm * 32 + mi * 16 + gid;
    int r1 = r0 + 8;
    bool v0 = r0 < E, v1 = r1 < E;
    int d0 = v0 ? __ldg(edst + r0) : 0;
    int d1 = v1 ? __ldg(edst + r1) : 0;
    const float* MI0 = msg_input + (size_t)r0 * H;
    const float* MI1 = msg_input + (size_t)r1 * H;
    float* MO0 = msg_out + (size_t)r0 * H;
    float* MO1 = msg_out + (size_t)r1 * H;
    float* SN0 = Snext + (size_t)d0 * H;
    float* SN1 = Snext + (size_t)d1 * H;
#pragma unroll
    for (int ni = 0; ni < 8; ni++) {
      int n = wn * 64 + ni * 8 + tig * 2;
      if (v0) {
        float2 m0 = *(const float2*)(MI0 + n);
        float o0 = fmaxf(acc[mi][ni][0] + m0.x, 0.f);
        float o1 = fmaxf(acc[mi][ni][1] + m0.y, 0.f);
        float2 o = {o0, o1};
        *(float2*)(MO0 + n) = o;
        red_add2(SN0 + n, o0, o1);
      }
      if (v1) {
        float2 m1 = *(const float2*)(MI1 + n);
        float o2 = fmaxf(acc[mi][ni][2] + m1.x, 0.f);
        float o3 = fmaxf(acc[mi][ni][3] + m1.y, 0.f);
        float2 o = {o2, o3};
        *(float2*)(MO1 + n) = o;
        red_add2(SN1 + n, o2, o3);
      }
    }
  }
}

// ---------------- output GEMM: BM=128, 512 thr, permuted A -------------------
// h = relu(concat-perm(S[n], x[n]) @ WoPerm^T + b_o); out[mol] += h / APM
__global__ __launch_bounds__(512, 1) void k_out_t(
    const float* __restrict__ x, const float* __restrict__ S,
    const __half* __restrict__ Wo_hi, const __half* __restrict__ Wo_lo,
    const float* __restrict__ b_o, float* __restrict__ out,
    int N, int APM)
{
  extern __shared__ __align__(16) char smc[];
  uint32_t sb = smem_u32(smc);
  int tid = threadIdx.x, wid = tid >> 5, lane = tid & 31;
  int wm = wid & 3, wn = wid >> 2;
  int gid = lane >> 2, tig = lane & 3;
  int bm = blockIdx.x * 128;

  int srow = tid >> 2;
  int skq  = (tid & 3) * 8;
  int node = bm + srow;
  bool nv = node < N;
  const float* Xp = x + (size_t)node * AF;
  const float* Sp = S + (size_t)node * H + skq;

  int bRow  = tid >> 1;
  int bHalf = tid & 1;
  const char* Wsrc = (const char*)((bHalf ? Wo_lo : Wo_hi) + (size_t)bRow * KO_PAD);
  uint32_t aStoreOff = (uint32_t)(srow * 80 + skq * 2);

  int lrow = (lane & 7) + ((lane >> 3) & 1) * 8;
  int lcol = (lane >> 4) * 8;
  int selB = lane >> 3;
  uint32_t bLaneBase = 40960u + (uint32_t)((selB >> 1) * 20480)
                     + (uint32_t)((wn * 64 + (lane & 7)) * 80)
                     + (uint32_t)((selB & 1) * 16);

  float acc[2][8][4];
#pragma unroll
  for (int mi = 0; mi < 2; mi++)
#pragma unroll
    for (int ni = 0; ni < 8; ni++)
#pragma unroll
      for (int q = 0; q < 4; q++) acc[mi][ni][q] = 0.f;

  float ga[8];

  auto cpB = [&](int kc, int buf) {
    const char* s = Wsrc + kc * 64;
    uint32_t d = sb + (bHalf ? M_BL(buf) : M_BH(buf)) + (uint32_t)bRow * 80;
#pragma unroll
    for (int i = 0; i < 4; i++) CP16(d + i * 16, s + i * 16);
    CP_COMMIT();
  };
  // k layout: [0,256) = S row (vector loads), [256,295) = x row, rest 0
  auto gatherA = [&](int kc) {
    if (kc < 8) {
      if (nv) {
        float4 v0 = *(const float4*)(Sp + kc * 32);
        float4 v1 = *(const float4*)(Sp + kc * 32 + 4);
        ga[0] = v0.x; ga[1] = v0.y; ga[2] = v0.z; ga[3] = v0.w;
        ga[4] = v1.x; ga[5] = v1.y; ga[6] = v1.z; ga[7] = v1.w;
      } else {
#pragma unroll
        for (int j = 0; j < 8; j++) ga[j] = 0.f;
      }
    } else {
#pragma unroll
      for (int j = 0; j < 8; j++) {
        int idx = kc * 32 + skq + j - H;
        ga[j] = (nv && idx < AF) ? Xp[idx] : 0.f;
      }
    }
  };
  auto storeA = [&](int buf) {
    __half hh[8], ll[8];
#pragma unroll
    for (int j = 0; j < 8; j++) {
      __half h = __float2half_rn(ga[j]);
      hh[j] = h;
      ll[j] = __float2half_rn(ga[j] - __half2float(h));
    }
    *(uint4*)(smc + M_AH(buf) + aStoreOff) = *(uint4*)hh;
    *(uint4*)(smc + M_AL(buf) + aStoreOff) = *(uint4*)ll;
  };

  cpB(0, 0);
  gatherA(0);
  cpB(1, 1);
  storeA(0);
  gatherA(1);
  CP_WAIT(1);
  __syncthreads();

#pragma unroll 1
  for (int kc = 0; kc < 10; kc++) {
    int cur = kc & 1;
    uint32_t aH = sb + M_AH(cur), aL = sb + M_AL(cur);
    uint32_t bBase = sb + bLaneBase + (uint32_t)cur * 40960u;
#pragma unroll
    for (int ks = 0; ks < 2; ks++) {
      uint32_t a_hi[2][4], a_lo[2][4];
#pragma unroll
      for (int mi = 0; mi < 2; mi++) {
        uint32_t off = (uint32_t)((wm * 32 + mi * 16 + lrow) * LDA2 + ks * 16 + lcol) * 2;
        ldm4(a_hi[mi], aH + off);
        ldm4(a_lo[mi], aL + off);
      }
#pragma unroll
      for (int ni = 0; ni < 8; ni++) {
        uint32_t bf[4];
        ldm4(bf, bBase + (uint32_t)(ks * 32 + ni * 640));
#pragma unroll
        for (int mi = 0; mi < 2; mi++) {
          mma16816(acc[mi][ni], a_hi[mi], bf);
          mma16816(acc[mi][ni], a_hi[mi], bf + 2);
          mma16816(acc[mi][ni], a_lo[mi], bf);
        }
      }
    }
    if (kc < 9) storeA(cur ^ 1);
    CP_WAIT(0);
    __syncthreads();
    if (kc < 8) { cpB(kc + 2, cur); gatherA(kc + 2); }
  }

  float inv = 1.f / (float)APM;
#pragma unroll
  for (int mi = 0; mi < 2; mi++) {
    int r0 = bm + wm * 32 + mi * 16 + gid;
    int r1 = r0 + 8;
    bool v0 = r0 < N, v1 = r1 < N;
    int mol0 = v0 ? (r0 / APM) : 0;
    int mol1 = v1 ? (r1 / APM) : 0;
    float* O0 = out + (size_t)mol0 * H;
    float* O1 = out + (size_t)mol1 * H;
#pragma unroll
    for (int ni = 0; ni < 8; ni++) {
      int n = wn * 64 + ni * 8 + tig * 2;
      float2 bo = *(const float2*)(b_o + n);
      if (v0) {
        float o0 = fmaxf(acc[mi][ni][0] + bo.x, 0.f) * inv;
        float o1 = fmaxf(acc[mi][ni][1] + bo.y, 0.f) * inv;
        red_add2(O0 + n, o0, o1);
      }
      if (v1) {
        float o2 = fmaxf(acc[mi][ni][2] + bo.x, 0.f) * inv;
        float o3 = fmaxf(acc[mi][ni][3] + bo.y, 0.f) * inv;
        red_add2(O1 + n, o2, o3);
      }
    }
  }
}

// ---------------- host ---------------------------------------------------------
extern "C" void kernel_launch(void* const* d_in, const int* in_sizes, int n_in,
                              void* d_out, int out_size) {
  const float* x    = (const float*)d_in[0];
  const float* bond = (const float*)d_in[1];
  const float* W_i  = (const float*)d_in[2];
  const float* W_h  = (const float*)d_in[3];
  const float* W_o  = (const float*)d_in[4];
  const float* b_o  = (const float*)d_in[5];
  const int*   esrc = (const int*)d_in[6];
  const int*   edst = (const int*)d_in[7];
  (void)n_in;

  int N   = in_sizes[0] / AF;
  int E   = in_sizes[1] / BF;
  int NM  = out_size / H;
  int APM = N / NM;

  float *msg_input, *msgA, *msgB, *S0, *S1;
  __half *WiH, *WiL, *WhH, *WhL, *WoH, *WoL;
  cudaGetSymbolAddress((void**)&msg_input, g_msg_input);
  cudaGetSymbolAddress((void**)&msgA, g_msgA);
  cudaGetSymbolAddress((void**)&msgB, g_msgB);
  cudaGetSymbolAddress((void**)&S0, g_S0);
  cudaGetSymbolAddress((void**)&S1, g_S1);
  cudaGetSymbolAddress((void**)&WiH, g_Wi_hi);
  cudaGetSymbolAddress((void**)&WiL, g_Wi_lo);
  cudaGetSymbolAddress((void**)&WhH, g_Wh_hi);
  cudaGetSymbolAddress((void**)&WhL, g_Wh_lo);
  cudaGetSymbolAddress((void**)&WoH, g_Wo_hi);
  cudaGetSymbolAddress((void**)&WoL, g_Wo_lo);

  cudaFuncSetAttribute(k_init_t, cudaFuncAttributeMaxDynamicSharedMemorySize, SMEM_MSG);
  cudaFuncSetAttribute(k_msg, cudaFuncAttributeMaxDynamicSharedMemorySize, SMEM_MSG);
  cudaFuncSetAttribute(k_out_t, cudaFuncAttributeMaxDynamicSharedMemorySize, SMEM_MSG);

  size_t sbytes = (size_t)N * H * sizeof(float);

  cudaMemsetAsync(d_out, 0, (size_t)out_size * sizeof(float));
  k_prep<<<(H * KO_PAD + 255) / 256, 256>>>(WiH, WiL, W_i, WhH, WhL, W_h, WoH, WoL, W_o);
  cudaMemsetAsync(S0, 0, sbytes);

  int nblk_e = (E + 127) / 128;
  k_init_t<<<nblk_e, 512, SMEM_MSG>>>(x, bond, esrc, edst, WiH, WiL, msg_input, S0, E);

  float* cur = msg_input;    // iteration 0 gathers rev from msg_input (+relu)
  float* nxt = msgA;
  float* Scur = S0;
  float* Snext = S1;
  for (int it = 0; it < 5; it++) {
    cudaMemsetAsync(Snext, 0, sbytes);
    k_msg<<<nblk_e, 512, SMEM_MSG>>>(Scur, cur, msg_input, WhH, WhL,
                                     esrc, edst, nxt, Snext, E, it == 0 ? 1 : 0);
    cur = nxt;
    nxt = (cur == msgA) ? msgB : msgA;
    float* t = Scur; Scur = Snext; Snext = t;
  }

  int nblk_n = (N + 127) / 128;
  k_out_t<<<nblk_n, 512, SMEM_MSG>>>(x, Scur, WoH, WoL, b_o, (float*)d_out, N, APM);
}

// round 16
// speedup vs baseline: 1.1016x; 1.0102x over previous
#include <cuda_runtime.h>
#include <cuda_fp16.h>
#include <cstdint>
#include <cstddef>

#define H        256
#define AF       39
#define BF       11
#define KI       50
#define KIPAD    64
#define KO_REAL  295
#define KO_PAD   320
#define EMAX     380000
#define NMAX     200000
#define LDA2     40            // 32 k + 8 pad (halves)

// ---- shared smem layout for all BM=128 / 512-thr kernels ----
#define M_AH(b)    ((b) * 20480)
#define M_AL(b)    ((b) * 20480 + 10240)
#define M_BH(b)    (40960 + (b) * 40960)
#define M_BL(b)    (40960 + (b) * 40960 + 20480)
#define SMEM_MSG   122880

// ---------------- scratch (device globals) ----------------------------------
__device__ float g_msg_input[(size_t)EMAX * H];
__device__ float g_msgA[(size_t)EMAX * H];
__device__ float g_msgB[(size_t)EMAX * H];
__device__ float g_S0[(size_t)NMAX * H];
__device__ float g_S1[(size_t)NMAX * H];
__device__ __half g_Wi_hi[H * KIPAD];
__device__ __half g_Wi_lo[H * KIPAD];
__device__ __half g_Wh_hi[H * H];
__device__ __half g_Wh_lo[H * H];
__device__ __half g_Wo_hi[H * KO_PAD];
__device__ __half g_Wo_lo[H * KO_PAD];

// ---------------- helpers ----------------------------------------------------
__device__ __forceinline__ void red_add2(float* p, float a, float b) {
  asm volatile("red.global.add.v2.f32 [%0], {%1,%2};"
               :: "l"(p), "f"(a), "f"(b) : "memory");
}
__device__ __forceinline__ uint32_t smem_u32(const void* p) {
  return (uint32_t)__cvta_generic_to_shared(p);
}
__device__ __forceinline__ void ldm4(uint32_t* r, uint32_t addr) {
  asm volatile("ldmatrix.sync.aligned.m8n8.x4.shared.b16 {%0,%1,%2,%3}, [%4];"
               : "=r"(r[0]), "=r"(r[1]), "=r"(r[2]), "=r"(r[3]) : "r"(addr));
}
__device__ __forceinline__ void mma16816(float* c, const uint32_t* a, const uint32_t* b) {
  asm volatile("mma.sync.aligned.m16n8k16.row.col.f32.f16.f16.f32 "
               "{%0,%1,%2,%3}, {%4,%5,%6,%7}, {%8,%9}, {%0,%1,%2,%3};"
               : "+f"(c[0]), "+f"(c[1]), "+f"(c[2]), "+f"(c[3])
               : "r"(a[0]), "r"(a[1]), "r"(a[2]), "r"(a[3]),
                 "r"(b[0]), "r"(b[1]));
}
#define CP16(dst, src) \
  asm volatile("cp.async.cg.shared.global [%0], [%1], 16;" :: "r"(dst), "l"(src))
#define CP_COMMIT() asm volatile("cp.async.commit_group;" ::: "memory")
#define CP_WAIT(n)  asm volatile("cp.async.wait_group %0;" :: "n"(n) : "memory")

// ---------------- fused prep ---------------------------------------------------
// W_i -> hi/lo fp16 [256][64] (k padded); W_h hi/lo; W_o k-permuted [S|x|pad]
__global__ void k_prep(__half* __restrict__ WiH, __half* __restrict__ WiL,
                       const float* __restrict__ W_i,
                       __half* __restrict__ WhH, __half* __restrict__ WhL,
                       const float* __restrict__ W_h,
                       __half* __restrict__ WoH, __half* __restrict__ WoL,
                       const float* __restrict__ W_o) {
  int idx = blockIdx.x * 256 + threadIdx.x;
  if (idx < H * KIPAD) {
    int n = idx >> 6, k = idx & (KIPAD - 1);
    float v = (k < KI) ? W_i[n * KI + k] : 0.f;
    __half hh = __float2half_rn(v);
    WiH[idx] = hh;
    WiL[idx] = __float2half_rn(v - __half2float(hh));
  }
  if (idx < H * H) {
    float v = W_h[idx];
    __half hh = __float2half_rn(v);
    WhH[idx] = hh;
    WhL[idx] = __float2half_rn(v - __half2float(hh));
  }
  if (idx < H * KO_PAD) {
    int n = idx / KO_PAD, k = idx - n * KO_PAD;
    float v = 0.f;
    if (k < H)            v = W_o[n * KO_REAL + AF + k];
    else if (k < KO_REAL) v = W_o[n * KO_REAL + (k - H)];
    __half hh = __float2half_rn(v);
    WoH[idx] = hh;
    WoL[idx] = __float2half_rn(v - __half2float(hh));
  }
}

// ---------------- init: tensor-core fp16x3, K=64 (2 chunks) -------------------
__global__ __launch_bounds__(512, 1) void k_init_t(
    const float* __restrict__ x, const float* __restrict__ bond,
    const int* __restrict__ esrc, const int* __restrict__ edst,
    const __half* __restrict__ Wi_hi, const __half* __restrict__ Wi_lo,
    float* __restrict__ msg_input, float* __restrict__ S0, int E)
{
  extern __shared__ __align__(16) char smc[];
  uint32_t sb = smem_u32(smc);
  int tid = threadIdx.x, wid = tid >> 5, lane = tid & 31;
  int wm = wid & 3, wn = wid >> 2;
  int gid = lane >> 2, tig = lane & 3;
  int bm = blockIdx.x * 128;

  int srow = tid >> 2;
  int q    = tid & 3;
  int e = bm + srow;
  bool ev = e < E;
  int sidx = ev ? __ldg(esrc + e) : 0;
  const float* Xp = x    + (size_t)sidx * AF;
  const float* Bp = bond + (size_t)e * BF;

  int bRow  = tid >> 1;
  int bHalf = tid & 1;
  const char* Wsrc = (const char*)((bHalf ? Wi_lo : Wi_hi) + (size_t)bRow * KIPAD);
  uint32_t aStoreOff = (uint32_t)(srow * 80 + q * 16);

  int lrow = (lane & 7) + ((lane >> 3) & 1) * 8;
  int lcol = (lane >> 4) * 8;
  int selB = lane >> 3;
  uint32_t bLaneBase = 40960u + (uint32_t)((selB >> 1) * 20480)
                     + (uint32_t)((wn * 64 + (lane & 7)) * 80)
                     + (uint32_t)((selB & 1) * 16);

  float acc[2][8][4];
#pragma unroll
  for (int mi = 0; mi < 2; mi++)
#pragma unroll
    for (int ni = 0; ni < 8; ni++)
#pragma unroll
      for (int qq = 0; qq < 4; qq++) acc[mi][ni][qq] = 0.f;

  {
    uint32_t d0 = sb + (bHalf ? M_BL(0) : M_BH(0)) + (uint32_t)bRow * 80;
#pragma unroll
    for (int i = 0; i < 4; i++) CP16(d0 + i * 16, Wsrc + i * 16);
    CP_COMMIT();
    uint32_t d1 = sb + (bHalf ? M_BL(1) : M_BH(1)) + (uint32_t)bRow * 80;
#pragma unroll
    for (int i = 0; i < 4; i++) CP16(d1 + i * 16, Wsrc + 64 + i * 16);
    CP_COMMIT();
  }

#pragma unroll
  for (int kc = 0; kc < 2; kc++) {
    float a[8];
#pragma unroll
    for (int j = 0; j < 8; j++) {
      int k = kc * 32 + q * 8 + j;
      float v = 0.f;
      if (ev) {
        if (k < AF)      v = Xp[k];
        else if (k < KI) v = Bp[k - AF];
      }
      a[j] = v;
    }
    __half hh[8], ll[8];
#pragma unroll
    for (int j = 0; j < 8; j++) {
      __half h = __float2half_rn(a[j]);
      hh[j] = h;
      ll[j] = __float2half_rn(a[j] - __half2float(h));
    }
    *(uint4*)(smc + M_AH(kc) + aStoreOff) = *(uint4*)hh;
    *(uint4*)(smc + M_AL(kc) + aStoreOff) = *(uint4*)ll;
  }
  CP_WAIT(0);
  __syncthreads();

#pragma unroll
  for (int kc = 0; kc < 2; kc++) {
    uint32_t aH = sb + M_AH(kc), aL = sb + M_AL(kc);
    uint32_t bBase = sb + bLaneBase + (uint32_t)kc * 40960u;
#pragma unroll
    for (int ks = 0; ks < 2; ks++) {
      uint32_t a_hi[2][4], a_lo[2][4];
#pragma unroll
      for (int mi = 0; mi < 2; mi++) {
        uint32_t off = (uint32_t)((wm * 32 + mi * 16 + lrow) * LDA2 + ks * 16 + lcol) * 2;
        ldm4(a_hi[mi], aH + off);
        ldm4(a_lo[mi], aL + off);
      }
#pragma unroll
      for (int ni = 0; ni < 8; ni++) {
        uint32_t bf[4];
        ldm4(bf, bBase + (uint32_t)(ks * 32 + ni * 640));
#pragma unroll
        for (int mi = 0; mi < 2; mi++) {
          mma16816(acc[mi][ni], a_hi[mi], bf);
          mma16816(acc[mi][ni], a_hi[mi], bf + 2);
          mma16816(acc[mi][ni], a_lo[mi], bf);
        }
      }
    }
  }

#pragma unroll
  for (int mi = 0; mi < 2; mi++) {
    int r0 = bm + wm * 32 + mi * 16 + gid;
    int r1 = r0 + 8;
    bool v0 = r0 < E, v1 = r1 < E;
    int d0 = v0 ? __ldg(edst + r0) : 0;
    int d1 = v1 ? __ldg(edst + r1) : 0;
    float* MO0 = msg_input + (size_t)r0 * H;
    float* MO1 = msg_input + (size_t)r1 * H;
    float* SN0 = S0 + (size_t)d0 * H;
    float* SN1 = S0 + (size_t)d1 * H;
#pragma unroll
    for (int ni = 0; ni < 8; ni++) {
      int n = wn * 64 + ni * 8 + tig * 2;
      if (v0) {
        float2 o = {acc[mi][ni][0], acc[mi][ni][1]};
        *(float2*)(MO0 + n) = o;
        red_add2(SN0 + n, fmaxf(o.x, 0.f), fmaxf(o.y, 0.f));
      }
      if (v1) {
        float2 o = {acc[mi][ni][2], acc[mi][ni][3]};
        *(float2*)(MO1 + n) = o;
        red_add2(SN1 + n, fmaxf(o.x, 0.f), fmaxf(o.y, 0.f));
      }
    }
  }
}

// ---------------- message GEMM: round-10 pipeline, dead-write elision --------
// msg_out[e] = relu(msg_input[e] + (S[src[e]] - msg_cur[rev(e)]) @ W_h^T)
// store_msg==0 skips the msg_out stores (last iteration: only scatter is live)
__global__ __launch_bounds__(512, 1) void k_msg(
    const float* __restrict__ S, const float* __restrict__ msg_cur,
    const float* __restrict__ msg_input,
    const __half* __restrict__ Wh_hi, const __half* __restrict__ Wh_lo,
    const int* __restrict__ esrc, const int* __restrict__ edst,
    float* __restrict__ msg_out, float* __restrict__ Snext,
    int E, int relu_rev, int store_msg)
{
  extern __shared__ __align__(16) char smc[];
  uint32_t sb = smem_u32(smc);
  int tid = threadIdx.x, wid = tid >> 5, lane = tid & 31;
  int wm = wid & 3, wn = wid >> 2;
  int gid = lane >> 2, tig = lane & 3;
  int bm = blockIdx.x * 128;

  int srow = tid >> 2;
  int skq  = (tid & 3) * 8;
  int e = bm + srow;
  bool ev = e < E;
  int eh = E >> 1;
  int sidx = 0, ridx = 0;
  if (ev) { sidx = __ldg(esrc + e); ridx = (e < eh) ? (e + eh) : (e - eh); }
  const float* Sp = S       + (size_t)sidx * H + skq;
  const float* Rp = msg_cur + (size_t)ridx * H + skq;

  int bRow  = tid >> 1;
  int bHalf = tid & 1;
  const char* Wsrc = (const char*)((bHalf ? Wh_lo : Wh_hi) + (size_t)bRow * H);
  uint32_t aStoreOff = (uint32_t)(srow * 80 + skq * 2);

  int lrow = (lane & 7) + ((lane >> 3) & 1) * 8;
  int lcol = (lane >> 4) * 8;
  int selB = lane >> 3;
  uint32_t bLaneBase = 40960u + (uint32_t)((selB >> 1) * 20480)
                     + (uint32_t)((wn * 64 + (lane & 7)) * 80)
                     + (uint32_t)((selB & 1) * 16);

  float acc[2][8][4];
#pragma unroll
  for (int mi = 0; mi < 2; mi++)
#pragma unroll
    for (int ni = 0; ni < 8; ni++)
#pragma unroll
      for (int q = 0; q < 4; q++) acc[mi][ni][q] = 0.f;

  float4 ga0, ga1, gr0, gr1;

  auto cpB = [&](int kc, int buf) {
    const char* s = Wsrc + kc * 64;
    uint32_t d = sb + (bHalf ? M_BL(buf) : M_BH(buf)) + (uint32_t)bRow * 80;
#pragma unroll
    for (int i = 0; i < 4; i++) CP16(d + i * 16, s + i * 16);
    CP_COMMIT();
  };
  auto gatherA = [&](int kc) {
    if (ev) {
      ga0 = *(const float4*)(Sp + kc * 32);
      ga1 = *(const float4*)(Sp + kc * 32 + 4);
      gr0 = *(const float4*)(Rp + kc * 32);
      gr1 = *(const float4*)(Rp + kc * 32 + 4);
      if (relu_rev) {
        gr0.x = fmaxf(gr0.x, 0.f); gr0.y = fmaxf(gr0.y, 0.f);
        gr0.z = fmaxf(gr0.z, 0.f); gr0.w = fmaxf(gr0.w, 0.f);
        gr1.x = fmaxf(gr1.x, 0.f); gr1.y = fmaxf(gr1.y, 0.f);
        gr1.z = fmaxf(gr1.z, 0.f); gr1.w = fmaxf(gr1.w, 0.f);
      }
    } else {
      ga0 = ga1 = gr0 = gr1 = make_float4(0.f, 0.f, 0.f, 0.f);
    }
  };
  auto storeA = [&](int buf) {
    float a[8];
    a[0] = ga0.x - gr0.x; a[1] = ga0.y - gr0.y; a[2] = ga0.z - gr0.z; a[3] = ga0.w - gr0.w;
    a[4] = ga1.x - gr1.x; a[5] = ga1.y - gr1.y; a[6] = ga1.z - gr1.z; a[7] = ga1.w - gr1.w;
    __half hh[8], ll[8];
#pragma unroll
    for (int j = 0; j < 8; j++) {
      __half h = __float2half_rn(a[j]);
      hh[j] = h;
      ll[j] = __float2half_rn(a[j] - __half2float(h));
    }
    *(uint4*)(smc + M_AH(buf) + aStoreOff) = *(uint4*)hh;
    *(uint4*)(smc + M_AL(buf) + aStoreOff) = *(uint4*)ll;
  };

  cpB(0, 0);
  gatherA(0);
  cpB(1, 1);
  storeA(0);
  gatherA(1);
  CP_WAIT(1);
  __syncthreads();

#pragma unroll 1
  for (int kc = 0; kc < 8; kc++) {
    int cur = kc & 1;
    uint32_t aH = sb + M_AH(cur), aL = sb + M_AL(cur);
    uint32_t bBase = sb + bLaneBase + (uint32_t)cur * 40960u;
#pragma unroll
    for (int ks = 0; ks < 2; ks++) {
      uint32_t a_hi[2][4], a_lo[2][4];
#pragma unroll
      for (int mi = 0; mi < 2; mi++) {
        uint32_t off = (uint32_t)((wm * 32 + mi * 16 + lrow) * LDA2 + ks * 16 + lcol) * 2;
        ldm4(a_hi[mi], aH + off);
        ldm4(a_lo[mi], aL + off);
      }
#pragma unroll
      for (int ni = 0; ni < 8; ni++) {
        uint32_t bf[4];
        ldm4(bf, bBase + (uint32_t)(ks * 32 + ni * 640));
#pragma unroll
        for (int mi = 0; mi < 2; mi++) {
          mma16816(acc[mi][ni], a_hi[mi], bf);
          mma16816(acc[mi][ni], a_hi[mi], bf + 2);
          mma16816(acc[mi][ni], a_lo[mi], bf);
        }
      }
    }
    if (kc < 7) storeA(cur ^ 1);
    CP_WAIT(0);
    __syncthreads();
    if (kc < 6) { cpB(kc + 2, cur); gatherA(kc + 2); }
  }

#pragma unroll
  for (int mi = 0; mi < 2; mi++) {
    int r0 = bm + wm * 32 + mi * 16 + gid;
    int r1 = r0 + 8;
    bool v0 = r0 < E, v1 = r1 < E;
    int d0 = v0 ? __ldg(edst + r0) : 0;
    int d1 = v1 ? __ldg(edst + r1) : 0;
    const float* MI0 = msg_input + (size_t)r0 * H;
    const float* MI1 = msg_input + (size_t)r1 * H;
    float* MO0 = msg_out + (size_t)r0 * H;
    float* MO1 = msg_out + (size_t)r1 * H;
    float* SN0 = Snext + (size_t)d0 * H;
    float* SN1 = Snext + (size_t)d1 * H;
#pragma unroll
    for (int ni = 0; ni < 8; ni++) {
      int n = wn * 64 + ni * 8 + tig * 2;
      if (v0) {
        float2 m0 = *(const float2*)(MI0 + n);
        float o0 = fmaxf(acc[mi][ni][0] + m0.x, 0.f);
        float o1 = fmaxf(acc[mi][ni][1] + m0.y, 0.f);
        if (store_msg) {
          float2 o = {o0, o1};
          *(float2*)(MO0 + n) = o;
        }
        red_add2(SN0 + n, o0, o1);
      }
      if (v1) {
        float2 m1 = *(const float2*)(MI1 + n);
        float o2 = fmaxf(acc[mi][ni][2] + m1.x, 0.f);
        float o3 = fmaxf(acc[mi][ni][3] + m1.y, 0.f);
        if (store_msg) {
          float2 o = {o2, o3};
          *(float2*)(MO1 + n) = o;
        }
        red_add2(SN1 + n, o2, o3);
      }
    }
  }
}

// ---------------- output GEMM: BM=128, 512 thr, permuted A -------------------
__global__ __launch_bounds__(512, 1) void k_out_t(
    const float* __restrict__ x, const float* __restrict__ S,
    const __half* __restrict__ Wo_hi, const __half* __restrict__ Wo_lo,
    const float* __restrict__ b_o, float* __restrict__ out,
    int N, int APM)
{
  extern __shared__ __align__(16) char smc[];
  uint32_t sb = smem_u32(smc);
  int tid = threadIdx.x, wid = tid >> 5, lane = tid & 31;
  int wm = wid & 3, wn = wid >> 2;
  int gid = lane >> 2, tig = lane & 3;
  int bm = blockIdx.x * 128;

  int srow = tid >> 2;
  int skq  = (tid & 3) * 8;
  int node = bm + srow;
  bool nv = node < N;
  const float* Xp = x + (size_t)node * AF;
  const float* Sp = S + (size_t)node * H + skq;

  int bRow  = tid >> 1;
  int bHalf = tid & 1;
  const char* Wsrc = (const char*)((bHalf ? Wo_lo : Wo_hi) + (size_t)bRow * KO_PAD);
  uint32_t aStoreOff = (uint32_t)(srow * 80 + skq * 2);

  int lrow = (lane & 7) + ((lane >> 3) & 1) * 8;
  int lcol = (lane >> 4) * 8;
  int selB = lane >> 3;
  uint32_t bLaneBase = 40960u + (uint32_t)((selB >> 1) * 20480)
                     + (uint32_t)((wn * 64 + (lane & 7)) * 80)
                     + (uint32_t)((selB & 1) * 16);

  float acc[2][8][4];
#pragma unroll
  for (int mi = 0; mi < 2; mi++)
#pragma unroll
    for (int ni = 0; ni < 8; ni++)
#pragma unroll
      for (int q = 0; q < 4; q++) acc[mi][ni][q] = 0.f;

  float ga[8];

  auto cpB = [&](int kc, int buf) {
    const char* s = Wsrc + kc * 64;
    uint32_t d = sb + (bHalf ? M_BL(buf) : M_BH(buf)) + (uint32_t)bRow * 80;
#pragma unroll
    for (int i = 0; i < 4; i++) CP16(d + i * 16, s + i * 16);
    CP_COMMIT();
  };
  auto gatherA = [&](int kc) {
    if (kc < 8) {
      if (nv) {
        float4 v0 = *(const float4*)(Sp + kc * 32);
        float4 v1 = *(const float4*)(Sp + kc * 32 + 4);
        ga[0] = v0.x; ga[1] = v0.y; ga[2] = v0.z; ga[3] = v0.w;
        ga[4] = v1.x; ga[5] = v1.y; ga[6] = v1.z; ga[7] = v1.w;
      } else {
#pragma unroll
        for (int j = 0; j < 8; j++) ga[j] = 0.f;
      }
    } else {
#pragma unroll
      for (int j = 0; j < 8; j++) {
        int idx = kc * 32 + skq + j - H;
        ga[j] = (nv && idx < AF) ? Xp[idx] : 0.f;
      }
    }
  };
  auto storeA = [&](int buf) {
    __half hh[8], ll[8];
#pragma unroll
    for (int j = 0; j < 8; j++) {
      __half h = __float2half_rn(ga[j]);
      hh[j] = h;
      ll[j] = __float2half_rn(ga[j] - __half2float(h));
    }
    *(uint4*)(smc + M_AH(buf) + aStoreOff) = *(uint4*)hh;
    *(uint4*)(smc + M_AL(buf) + aStoreOff) = *(uint4*)ll;
  };

  cpB(0, 0);
  gatherA(0);
  cpB(1, 1);
  storeA(0);
  gatherA(1);
  CP_WAIT(1);
  __syncthreads();

#pragma unroll 1
  for (int kc = 0; kc < 10; kc++) {
    int cur = kc & 1;
    uint32_t aH = sb + M_AH(cur), aL = sb + M_AL(cur);
    uint32_t bBase = sb + bLaneBase + (uint32_t)cur * 40960u;
#pragma unroll
    for (int ks = 0; ks < 2; ks++) {
      uint32_t a_hi[2][4], a_lo[2][4];
#pragma unroll
      for (int mi = 0; mi < 2; mi++) {
        uint32_t off = (uint32_t)((wm * 32 + mi * 16 + lrow) * LDA2 + ks * 16 + lcol) * 2;
        ldm4(a_hi[mi], aH + off);
        ldm4(a_lo[mi], aL + off);
      }
#pragma unroll
      for (int ni = 0; ni < 8; ni++) {
        uint32_t bf[4];
        ldm4(bf, bBase + (uint32_t)(ks * 32 + ni * 640));
#pragma unroll
        for (int mi = 0; mi < 2; mi++) {
          mma16816(acc[mi][ni], a_hi[mi], bf);
          mma16816(acc[mi][ni], a_hi[mi], bf + 2);
          mma16816(acc[mi][ni], a_lo[mi], bf);
        }
      }
    }
    if (kc < 9) storeA(cur ^ 1);
    CP_WAIT(0);
    __syncthreads();
    if (kc < 8) { cpB(kc + 2, cur); gatherA(kc + 2); }
  }

  float inv = 1.f / (float)APM;
#pragma unroll
  for (int mi = 0; mi < 2; mi++) {
    int r0 = bm + wm * 32 + mi * 16 + gid;
    int r1 = r0 + 8;
    bool v0 = r0 < N, v1 = r1 < N;
    int mol0 = v0 ? (r0 / APM) : 0;
    int mol1 = v1 ? (r1 / APM) : 0;
    float* O0 = out + (size_t)mol0 * H;
    float* O1 = out + (size_t)mol1 * H;
#pragma unroll
    for (int ni = 0; ni < 8; ni++) {
      int n = wn * 64 + ni * 8 + tig * 2;
      float2 bo = *(const float2*)(b_o + n);
      if (v0) {
        float o0 = fmaxf(acc[mi][ni][0] + bo.x, 0.f) * inv;
        float o1 = fmaxf(acc[mi][ni][1] + bo.y, 0.f) * inv;
        red_add2(O0 + n, o0, o1);
      }
      if (v1) {
        float o2 = fmaxf(acc[mi][ni][2] + bo.x, 0.f) * inv;
        float o3 = fmaxf(acc[mi][ni][3] + bo.y, 0.f) * inv;
        red_add2(O1 + n, o2, o3);
      }
    }
  }
}

// ---------------- host ---------------------------------------------------------
extern "C" void kernel_launch(void* const* d_in, const int* in_sizes, int n_in,
                              void* d_out, int out_size) {
  const float* x    = (const float*)d_in[0];
  const float* bond = (const float*)d_in[1];
  const float* W_i  = (const float*)d_in[2];
  const float* W_h  = (const float*)d_in[3];
  const float* W_o  = (const float*)d_in[4];
  const float* b_o  = (const float*)d_in[5];
  const int*   esrc = (const int*)d_in[6];
  const int*   edst = (const int*)d_in[7];
  (void)n_in;

  int N   = in_sizes[0] / AF;
  int E   = in_sizes[1] / BF;
  int NM  = out_size / H;
  int APM = N / NM;

  float *msg_input, *msgA, *msgB, *S0, *S1;
  __half *WiH, *WiL, *WhH, *WhL, *WoH, *WoL;
  cudaGetSymbolAddress((void**)&msg_input, g_msg_input);
  cudaGetSymbolAddress((void**)&msgA, g_msgA);
  cudaGetSymbolAddress((void**)&msgB, g_msgB);
  cudaGetSymbolAddress((void**)&S0, g_S0);
  cudaGetSymbolAddress((void**)&S1, g_S1);
  cudaGetSymbolAddress((void**)&WiH, g_Wi_hi);
  cudaGetSymbolAddress((void**)&WiL, g_Wi_lo);
  cudaGetSymbolAddress((void**)&WhH, g_Wh_hi);
  cudaGetSymbolAddress((void**)&WhL, g_Wh_lo);
  cudaGetSymbolAddress((void**)&WoH, g_Wo_hi);
  cudaGetSymbolAddress((void**)&WoL, g_Wo_lo);

  cudaFuncSetAttribute(k_init_t, cudaFuncAttributeMaxDynamicSharedMemorySize, SMEM_MSG);
  cudaFuncSetAttribute(k_msg, cudaFuncAttributeMaxDynamicSharedMemorySize, SMEM_MSG);
  cudaFuncSetAttribute(k_out_t, cudaFuncAttributeMaxDynamicSharedMemorySize, SMEM_MSG);

  size_t sbytes = (size_t)N * H * sizeof(float);

  cudaMemsetAsync(d_out, 0, (size_t)out_size * sizeof(float));
  k_prep<<<(H * KO_PAD + 255) / 256, 256>>>(WiH, WiL, W_i, WhH, WhL, W_h, WoH, WoL, W_o);
  cudaMemsetAsync(S0, 0, sbytes);

  int nblk_e = (E + 127) / 128;
  k_init_t<<<nblk_e, 512, SMEM_MSG>>>(x, bond, esrc, edst, WiH, WiL, msg_input, S0, E);

  float* cur = msg_input;    // iteration 0 gathers rev from msg_input (+relu)
  float* nxt = msgA;
  float* Scur = S0;
  float* Snext = S1;
  for (int it = 0; it < 5; it++) {
    cudaMemsetAsync(Snext, 0, sbytes);
    k_msg<<<nblk_e, 512, SMEM_MSG>>>(Scur, cur, msg_input, WhH, WhL,
                                     esrc, edst, nxt, Snext, E,
                                     it == 0 ? 1 : 0,     // relu_rev
                                     it == 4 ? 0 : 1);    // store_msg (dead on last)
    cur = nxt;
    nxt = (cur == msgA) ? msgB : msgA;
    float* t = Scur; Scur = Snext; Snext = t;
  }

  int nblk_n = (N + 127) / 128;
  k_out_t<<<nblk_n, 512, SMEM_MSG>>>(x, Scur, WoH, WoL, b_o, (float*)d_out, N, APM);
}